// round 11
// baseline (speedup 1.0000x reference)
#include <cuda_runtime.h>
#include <cuda_bf16.h>
#include <cstdint>
#include <cstddef>

// MultiLayerLSTM via mma.sync (bf16 m16n8k16), fp32 bf16-split.
// A' = [batch-hi(64); batch-lo(64)] (M=128), N=32 gate rows/CTA.
// 256 thr/CTA (R9 shell). NEW: per-chunk fine-grained acquire-polling on the
// producing counter group (rotated by own group), release-doorbell arrival,
// 256-thread epilogue, W ldmatrix x4.

#define T_ 1024
#define B_ 64
#define C_ 256
#define H_ 512
#define NTHR_ 256
#define GRID_ 128

// ---- shared memory byte offsets ----
#define OFF_BS  0                  // 32 float biases
#define OFF_GR  128                // 64 x 33 float gate matrix
#define OFF_A   9216               // 2 x 16KB A' tiles (SW128)
#define OFF_WH  41984              // 16 x 4KB Whi chunk tiles
#define OFF_WL  107520             // 16 x 4KB Wlo chunk tiles
#define SMEM_BYTES 173056

typedef __nv_bfloat16 bf16;

static __device__ __align__(256) bf16 g_xhi[(size_t)T_ * B_ * C_];
static __device__ __align__(256) bf16 g_xlo[(size_t)T_ * B_ * C_];
static __device__ __align__(256) bf16 g_y0hi[(size_t)T_ * B_ * H_];
static __device__ __align__(256) bf16 g_y0lo[(size_t)T_ * B_ * H_];
static __device__ __align__(256) bf16 g_h1hi[(size_t)T_ * B_ * H_];
static __device__ __align__(256) bf16 g_h1lo[(size_t)T_ * B_ * H_];
static __device__ __align__(256) bf16 g_h00hi[B_ * H_], g_h00lo[B_ * H_];
static __device__ __align__(256) bf16 g_h01hi[B_ * H_], g_h01lo[B_ * H_];
static __device__ int g_bars0[8 * 32];
static __device__ int g_bars1[8 * 32];

__global__ void prep_kernel(const float* __restrict__ x,
                            const float* __restrict__ h00,
                            const float* __restrict__ h01) {
    const size_t stride = (size_t)gridDim.x * blockDim.x;
    const size_t i0 = (size_t)blockIdx.x * blockDim.x + threadIdx.x;
    const size_t nx = (size_t)T_ * B_ * C_;
    for (size_t p = i0; p < nx; p += stride) {
        float v = x[p];
        bf16 h = __float2bfloat16(v);
        g_xhi[p] = h;
        g_xlo[p] = __float2bfloat16(v - __bfloat162float(h));
    }
    for (size_t p = i0; p < (size_t)B_ * H_; p += stride) {
        float v = h00[p];
        bf16 h = __float2bfloat16(v);
        g_h00hi[p] = h;
        g_h00lo[p] = __float2bfloat16(v - __bfloat162float(h));
        v = h01[p];
        h = __float2bfloat16(v);
        g_h01hi[p] = h;
        g_h01lo[p] = __float2bfloat16(v - __bfloat162float(h));
    }
    if (blockIdx.x == 0 && threadIdx.x < 8) {
        g_bars0[threadIdx.x * 32] = 0;
        g_bars1[threadIdx.x * 32] = 0;
    }
}

__device__ __forceinline__ uint32_t smem_u32(const void* p) {
    uint32_t a;
    asm("{ .reg .u64 t; cvta.to.shared.u64 t, %1; cvt.u32.u64 %0, t; }"
        : "=r"(a) : "l"(p));
    return a;
}
__device__ __forceinline__ int ld_acq(const int* p) {
    int v;
    asm volatile(
        "{ .reg .u64 a; cvta.to.global.u64 a, %1; "
        "ld.acquire.gpu.global.b32 %0, [a]; }"
        : "=r"(v) : "l"(p) : "memory");
    return v;
}
__device__ __forceinline__ void red_rel(int* p) {
    asm volatile(
        "{ .reg .u64 a; cvta.to.global.u64 a, %1; "
        "red.release.gpu.global.add.u32 [a], %0; }"
        :: "r"(1), "l"(p) : "memory");
}
__device__ __forceinline__ void ldsm4(uint32_t addr, uint32_t* r) {
    asm volatile("ldmatrix.sync.aligned.m8n8.x4.shared.b16 {%0,%1,%2,%3}, [%4];"
                 : "=r"(r[0]), "=r"(r[1]), "=r"(r[2]), "=r"(r[3]) : "r"(addr));
}
__device__ __forceinline__ void mma16816(float* c, const uint32_t* a,
                                         const uint32_t* b) {
    asm volatile(
        "mma.sync.aligned.m16n8k16.row.col.f32.bf16.bf16.f32 "
        "{%0,%1,%2,%3}, {%4,%5,%6,%7}, {%8,%9}, {%0,%1,%2,%3};"
        : "+f"(c[0]), "+f"(c[1]), "+f"(c[2]), "+f"(c[3])
        : "r"(a[0]), "r"(a[1]), "r"(a[2]), "r"(a[3]), "r"(b[0]), "r"(b[1]));
}
__device__ __forceinline__ float sigf(float v) { return 1.0f / (1.0f + __expf(-v)); }
__device__ __forceinline__ float tanhe(float v) {
    const float e = __expf(2.0f * v);
    return 1.0f - 2.0f / (e + 1.0f);
}

extern __shared__ char smem8[];

__device__ __forceinline__ void ldgA(const bf16* __restrict__ shi,
                                     const bf16* __restrict__ slo,
                                     int rs, int col0, int tid, uint4* v) {
    #pragma unroll
    for (int it = 0; it < 4; it++) {
        const int seg = it * NTHR_ + tid;
        const int row = seg >> 3, s8 = seg & 7;
        const bf16* src = (row < 64 ? shi + (size_t)row * rs
                                    : slo + (size_t)(row - 64) * rs) + col0 + s8 * 8;
        v[it] = *(const uint4*)src;
    }
}
__device__ __forceinline__ void stsA(char* abuf, int tid, const uint4* v) {
    #pragma unroll
    for (int it = 0; it < 4; it++) {
        const int seg = it * NTHR_ + tid;
        const int row = seg >> 3, s8 = seg & 7;
        const uint32_t bo = row * 128 + s8 * 16;
        const uint32_t sw = bo ^ ((bo >> 3) & 0x70);
        *(uint4*)(abuf + sw) = v[it];
    }
}

// resolve chunk q of this step: source, k-offset, weight tile, dependency
__device__ __forceinline__ void resolve_chunk(
    int role, int q, int t, int grp,
    const bf16** shi, const bf16** slo, int* rs, int* col0, int* wc,
    const int** ctr, int* targ)
{
    if (role == 0) {
        if (q < 4) {                       // x part, no dependency
            *shi = g_xhi + (size_t)t * B_ * C_;
            *slo = g_xlo + (size_t)t * B_ * C_;
            *rs = C_; *col0 = q * 64; *wc = q; *ctr = nullptr; *targ = 0;
        } else {                           // own h part
            const int g = (q - 4 + grp) & 7;
            if (t == 0) { *shi = g_h00hi; *slo = g_h00lo; }
            else {
                *shi = g_y0hi + (size_t)(t - 1) * B_ * H_;
                *slo = g_y0lo + (size_t)(t - 1) * B_ * H_;
            }
            *rs = H_; *col0 = g * 64; *wc = 4 + g;
            *ctr = g_bars0 + g * 32; *targ = t * 8;
        }
    } else {
        if (q < 8) {                       // own h part
            const int g = (q + grp) & 7;
            if (t == 0) { *shi = g_h01hi; *slo = g_h01lo; }
            else {
                *shi = g_h1hi + (size_t)(t - 1) * B_ * H_;
                *slo = g_h1lo + (size_t)(t - 1) * B_ * H_;
            }
            *rs = H_; *col0 = g * 64; *wc = 8 + g;
            *ctr = g_bars1 + g * 32; *targ = t * 8;
        } else {                           // y0 part (layer0 step t output)
            const int g = (q - 8 + grp) & 7;
            *shi = g_y0hi + (size_t)t * B_ * H_;
            *slo = g_y0lo + (size_t)t * B_ * H_;
            *rs = H_; *col0 = g * 64; *wc = g;
            *ctr = g_bars0 + g * 32; *targ = (t + 1) * 8;
        }
    }
}

__global__ void __launch_bounds__(NTHR_, 1) lstm_kernel(
    const float* __restrict__ x,
    const float* __restrict__ h00, const float* __restrict__ c00,
    const float* __restrict__ h01, const float* __restrict__ c01,
    const float* __restrict__ Wih0, const float* __restrict__ Whh0,
    const float* __restrict__ bih0, const float* __restrict__ bhh0,
    const float* __restrict__ Wih1, const float* __restrict__ Whh1,
    const float* __restrict__ bih1, const float* __restrict__ bhh1,
    float* out)
{
    const int tid  = threadIdx.x;
    const int wid  = tid >> 5;
    const int lid  = tid & 31;
    const int bid  = blockIdx.x;
    const int role = bid >> 6;            // 0: layer0, 1: layer1
    const int j0   = (bid & 63) * 8;
    const int grp  = (bid & 63) >> 3;

    const uint32_t sb = smem_u32(smem8);
    float* Bs = (float*)(smem8 + OFF_BS);
    float* Gr = (float*)(smem8 + OFF_GR);   // [64][33]

    const int KX = role ? H_ : C_;
    const int K  = KX + H_;
    const float* Wx    = role ? Wih1 : Wih0;
    const float* Wh    = role ? Whh1 : Whh0;
    const float* bi    = role ? bih1 : bih0;
    const float* bh    = role ? bhh1 : bhh0;
    const float* cinit = role ? c01 : c00;

    // ---- one-time: split weights into SW128 chunk tiles (hi, lo) ----
    for (int idx = tid; idx < 32 * K; idx += NTHR_) {
        const int n = idx / K, k = idx - n * K;
        const int gr = (n >> 3) * H_ + j0 + (n & 7);
        const float v = (k < KX) ? Wx[(size_t)gr * KX + k]
                                 : Wh[(size_t)gr * H_ + (k - KX)];
        const bf16 hb = __float2bfloat16(v);
        const bf16 lb = __float2bfloat16(v - __bfloat162float(hb));
        const int wc = k >> 6, kk = k & 63;
        const uint32_t bo = n * 128 + kk * 2;
        const uint32_t sw = bo ^ ((bo >> 3) & 0x70);
        *(bf16*)(smem8 + OFF_WH + wc * 4096 + sw) = hb;
        *(bf16*)(smem8 + OFF_WL + wc * 4096 + sw) = lb;
    }
    if (tid < 32) {
        const int gr = (tid >> 3) * H_ + j0 + (tid & 7);
        Bs[tid] = bi[gr] + bh[gr];
    }
    // per-thread cells: m = tid&63, gates jp..jp+1
    const int mcell = tid & 63;
    const int jp = (tid >> 6) * 2;
    float creg[2];
    creg[0] = cinit[(size_t)mcell * H_ + j0 + jp];
    creg[1] = cinit[(size_t)mcell * H_ + j0 + jp + 1];
    __syncthreads();

    // warp decomposition: 4 m-slabs x 2 n-slabs
    const int mw = wid & 3;
    const int nw = wid >> 2;
    const int jA = lid >> 3, rA = lid & 7;
    const int rowA  = ((jA & 1) << 3) + rA;
    const int colA2 = (jA >> 1) << 4;
    const uint32_t swA = (uint32_t)rA << 4;
    const int jB = (lid >> 3) & 1, rB = lid & 7;
    const int colB2 = jB << 4;
    const uint32_t swB = (uint32_t)rB << 4;
    const uint32_t aHiBase = (uint32_t)(16 * mw + rowA) * 128;
    const uint32_t aLoBase = (uint32_t)(64 + 16 * mw + rowA) * 128;
    // merged W x4: lanes 0-15 -> n-tile0, lanes 16-31 -> n-tile1
    const uint32_t bRowSel = (uint32_t)(16 * nw + ((lid & 16) ? 8 : 0) + rB) * 128;

    float* yout = out;
    float* h1f  = out + (size_t)T_ * B_ * H_;
    float* c1f  = h1f + B_ * H_;
    float* h2f  = c1f + B_ * H_;
    float* c2f  = h2f + B_ * H_;
    float* hTd  = role ? h2f : h1f;
    float* cTd  = role ? c2f : c1f;
    int* actr   = (role ? g_bars1 : g_bars0) + grp * 32;

    const int NCH = role ? 16 : 12;

    for (int t = 0; t < T_; t++) {
        float acc[2][2][4];
        #pragma unroll
        for (int i = 0; i < 2; i++)
            #pragma unroll
            for (int j = 0; j < 2; j++)
                #pragma unroll
                for (int q = 0; q < 4; q++) acc[i][j][q] = 0.0f;

        // current chunk descriptor
        const bf16 *shi, *slo;
        int rs, col0, wcc;
        const int* ctr; int targ;
        resolve_chunk(role, 0, t, grp, &shi, &slo, &rs, &col0, &wcc, &ctr, &targ);
        if (ctr) while (ld_acq(ctr) < targ) { }
        {
            uint4 v[4];
            ldgA(shi, slo, rs, col0, tid, v);
            stsA(smem8 + OFF_A, tid, v);
        }

        int ab = 0;
        #pragma unroll 1
        for (int q = 0; q < NCH; q++) {
            __syncthreads();              // staged buffer visible; other free
            uint4 v[4];
            const bool pf = (q + 1 < NCH);
            const bf16 *nhi = nullptr, *nlo = nullptr;
            int nrs = 0, ncol = 0, nwc = 0;
            if (pf) {
                const int* nctr; int ntarg;
                resolve_chunk(role, q + 1, t, grp, &nhi, &nlo, &nrs, &ncol,
                              &nwc, &nctr, &ntarg);
                if (nctr) while (ld_acq(nctr) < ntarg) { }
                ldgA(nhi, nlo, nrs, ncol, tid, v);
            }

            // ---- compute chunk (wcc): 4 k-steps ----
            {
                const uint32_t aBase = sb + OFF_A + ab * 16384;
                const uint32_t whB   = sb + OFF_WH + (uint32_t)wcc * 4096;
                const uint32_t wlB   = sb + OFF_WL + (uint32_t)wcc * 4096;
                #pragma unroll
                for (int ks = 0; ks < 4; ks++) {
                    const uint32_t kA = (uint32_t)((ks * 32 + colA2) ^ (int)swA);
                    const uint32_t kB = (uint32_t)((ks * 32 + colB2) ^ (int)swB);
                    uint32_t ah[4], al[4], bhv[4], blv[4];
                    ldsm4(aBase + aHiBase + kA, ah);
                    ldsm4(aBase + aLoBase + kA, al);
                    ldsm4(whB + bRowSel + kB, bhv);
                    ldsm4(wlB + bRowSel + kB, blv);
                    mma16816(acc[0][0], ah, bhv);
                    mma16816(acc[0][1], ah, bhv + 2);
                    mma16816(acc[1][0], al, bhv);
                    mma16816(acc[1][1], al, bhv + 2);
                    mma16816(acc[0][0], ah, blv);
                    mma16816(acc[0][1], ah, blv + 2);
                    mma16816(acc[1][0], al, blv);
                    mma16816(acc[1][1], al, blv + 2);
                }
            }
            if (pf) {
                stsA(smem8 + OFF_A + (ab ^ 1) * 16384, tid, v);
                wcc = nwc;
            }
            ab ^= 1;
        }
        __syncthreads();

        // ---- fold hi+lo m-tiles, write gates to Gr[64][33] ----
        {
            const int mrow = 16 * mw + (lid >> 2);
            const int col0w = 16 * nw + 2 * (lid & 3);
            #pragma unroll
            for (int nt = 0; nt < 2; nt++) {
                const int cc = col0w + nt * 8;
                Gr[mrow * 33 + cc]           = acc[0][nt][0] + acc[1][nt][0];
                Gr[mrow * 33 + cc + 1]       = acc[0][nt][1] + acc[1][nt][1];
                Gr[(mrow + 8) * 33 + cc]     = acc[0][nt][2] + acc[1][nt][2];
                Gr[(mrow + 8) * 33 + cc + 1] = acc[0][nt][3] + acc[1][nt][3];
            }
        }
        __syncthreads();

        // ---- pointwise (256 threads, 2 cells each) ----
        {
            const int m = mcell;
            float hv[2];
            #pragma unroll
            for (int u = 0; u < 2; u++) {
                const int jj = jp + u;
                float gi = Gr[m * 33 + jj]      + Bs[jj];
                float gf = Gr[m * 33 + 8 + jj]  + Bs[8 + jj];
                float gg = Gr[m * 33 + 16 + jj] + Bs[16 + jj];
                float go = Gr[m * 33 + 24 + jj] + Bs[24 + jj];
                gi = sigf(gi); gf = sigf(gf); gg = tanhe(gg); go = sigf(go);
                const float cv = gf * creg[u] + gi * gg;
                creg[u] = cv;
                hv[u] = go * tanhe(cv);
            }
            // split to bf16 hi/lo, pack 2 cells per u32
            const bf16 b0 = __float2bfloat16(hv[0]);
            const bf16 b1 = __float2bfloat16(hv[1]);
            const uint32_t phh = (uint32_t)__bfloat16_as_ushort(b0) |
                                 ((uint32_t)__bfloat16_as_ushort(b1) << 16);
            const bf16 l0 = __float2bfloat16(hv[0] - __bfloat162float(b0));
            const bf16 l1 = __float2bfloat16(hv[1] - __bfloat162float(b1));
            const uint32_t pll = (uint32_t)__bfloat16_as_ushort(l0) |
                                 ((uint32_t)__bfloat16_as_ushort(l1) << 16);
            const size_t off = (size_t)t * B_ * H_ + (size_t)m * H_ + j0 + jp;
            *(uint32_t*)((role ? g_h1hi : g_y0hi) + off) = phh;
            *(uint32_t*)((role ? g_h1lo : g_y0lo) + off) = pll;
            if (role)
                *(float2*)(yout + off) = make_float2(hv[0], hv[1]);
            if (t == T_ - 1) {
                const size_t foff = (size_t)m * H_ + j0 + jp;
                *(float2*)(hTd + foff) = make_float2(hv[0], hv[1]);
                *(float2*)(cTd + foff) = make_float2(creg[0], creg[1]);
            }
        }
        __syncthreads();
        if (tid == 0) red_rel(actr);
    }
}

extern "C" void kernel_launch(void* const* d_in, const int* in_sizes, int n_in,
                              void* d_out, int out_size) {
    (void)in_sizes; (void)n_in; (void)out_size;
    cudaFuncSetAttribute(lstm_kernel, cudaFuncAttributeMaxDynamicSharedMemorySize,
                         SMEM_BYTES);
    prep_kernel<<<1024, 256>>>((const float*)d_in[0], (const float*)d_in[1],
                               (const float*)d_in[3]);
    lstm_kernel<<<GRID_, NTHR_, SMEM_BYTES>>>(
        (const float*)d_in[0],
        (const float*)d_in[1], (const float*)d_in[2],
        (const float*)d_in[3], (const float*)d_in[4],
        (const float*)d_in[5], (const float*)d_in[6],
        (const float*)d_in[7], (const float*)d_in[8],
        (const float*)d_in[9], (const float*)d_in[10],
        (const float*)d_in[11], (const float*)d_in[12],
        (float*)d_out);
}

// round 12
// speedup vs baseline: 1.2336x; 1.2336x over previous
#include <cuda_runtime.h>
#include <cuda_bf16.h>
#include <cstdint>
#include <cstddef>

// MultiLayerLSTM via mma.sync (bf16 m16n8k16), fp32 bf16 3-product split.
// A' = [batch-hi(64); batch-lo(64)] (M=128), N=32 gate rows/CTA.
// 256 thr/CTA. cp.async 4-stage staging ring (3 chunks ahead), merged W
// ldmatrix x4, 256-thread epilogue. 64+64 CTAs, decoupled per-layer counters.

#define T_ 1024
#define B_ 64
#define C_ 256
#define H_ 512
#define NTHR_ 256
#define GRID_ 128

// ---- shared memory byte offsets ----
#define OFF_BS  0                  // 32 float biases
#define OFF_GR  128                // 64 x 33 float gate matrix
#define OFF_A   9216               // 4 x 16KB A' stage ring (SW128)
#define OFF_WH  74752              // 16 x 4KB Whi chunk tiles
#define OFF_WL  140288             // 16 x 4KB Wlo chunk tiles
#define SMEM_BYTES 205824

typedef __nv_bfloat16 bf16;

static __device__ __align__(256) bf16 g_xhi[(size_t)T_ * B_ * C_];
static __device__ __align__(256) bf16 g_xlo[(size_t)T_ * B_ * C_];
static __device__ __align__(256) bf16 g_y0hi[(size_t)T_ * B_ * H_];
static __device__ __align__(256) bf16 g_y0lo[(size_t)T_ * B_ * H_];
static __device__ __align__(256) bf16 g_h1hi[(size_t)T_ * B_ * H_];
static __device__ __align__(256) bf16 g_h1lo[(size_t)T_ * B_ * H_];
static __device__ __align__(256) bf16 g_h00hi[B_ * H_], g_h00lo[B_ * H_];
static __device__ __align__(256) bf16 g_h01hi[B_ * H_], g_h01lo[B_ * H_];
static __device__ int g_bars0[8 * 32];
static __device__ int g_bars1[8 * 32];

__global__ void prep_kernel(const float* __restrict__ x,
                            const float* __restrict__ h00,
                            const float* __restrict__ h01) {
    const size_t stride = (size_t)gridDim.x * blockDim.x;
    const size_t i0 = (size_t)blockIdx.x * blockDim.x + threadIdx.x;
    const size_t nx = (size_t)T_ * B_ * C_;
    for (size_t p = i0; p < nx; p += stride) {
        float v = x[p];
        bf16 h = __float2bfloat16(v);
        g_xhi[p] = h;
        g_xlo[p] = __float2bfloat16(v - __bfloat162float(h));
    }
    for (size_t p = i0; p < (size_t)B_ * H_; p += stride) {
        float v = h00[p];
        bf16 h = __float2bfloat16(v);
        g_h00hi[p] = h;
        g_h00lo[p] = __float2bfloat16(v - __bfloat162float(h));
        v = h01[p];
        h = __float2bfloat16(v);
        g_h01hi[p] = h;
        g_h01lo[p] = __float2bfloat16(v - __bfloat162float(h));
    }
    if (blockIdx.x == 0 && threadIdx.x < 8) {
        g_bars0[threadIdx.x * 32] = 0;
        g_bars1[threadIdx.x * 32] = 0;
    }
}

__device__ __forceinline__ uint32_t smem_u32(const void* p) {
    uint32_t a;
    asm("{ .reg .u64 t; cvta.to.shared.u64 t, %1; cvt.u32.u64 %0, t; }"
        : "=r"(a) : "l"(p));
    return a;
}
__device__ __forceinline__ void cp16(uint32_t daddr, const void* gptr) {
    asm volatile("cp.async.cg.shared.global [%0], [%1], 16;"
                 :: "r"(daddr), "l"(gptr) : "memory");
}
__device__ __forceinline__ void cp_commit() {
    asm volatile("cp.async.commit_group;" ::: "memory");
}
template <int N> __device__ __forceinline__ void cp_wait() {
    asm volatile("cp.async.wait_group %0;" :: "n"(N) : "memory");
}
__device__ __forceinline__ void ldsm4(uint32_t addr, uint32_t* r) {
    asm volatile("ldmatrix.sync.aligned.m8n8.x4.shared.b16 {%0,%1,%2,%3}, [%4];"
                 : "=r"(r[0]), "=r"(r[1]), "=r"(r[2]), "=r"(r[3]) : "r"(addr));
}
__device__ __forceinline__ void mma16816(float* c, const uint32_t* a,
                                         const uint32_t* b) {
    asm volatile(
        "mma.sync.aligned.m16n8k16.row.col.f32.bf16.bf16.f32 "
        "{%0,%1,%2,%3}, {%4,%5,%6,%7}, {%8,%9}, {%0,%1,%2,%3};"
        : "+f"(c[0]), "+f"(c[1]), "+f"(c[2]), "+f"(c[3])
        : "r"(a[0]), "r"(a[1]), "r"(a[2]), "r"(a[3]), "r"(b[0]), "r"(b[1]));
}
__device__ __forceinline__ float sigf(float v) { return 1.0f / (1.0f + __expf(-v)); }
__device__ __forceinline__ float tanhe(float v) {
    const float e = __expf(2.0f * v);
    return 1.0f - 2.0f / (e + 1.0f);
}

__device__ __forceinline__ void wait_bars(const int* bars, int tid, int target) {
    if (tid < 8) {
        volatile const int* p = bars + tid * 32;
        while (*p < target) { }
        __threadfence();
    }
    __syncthreads();
}

extern __shared__ char smem8[];

// issue chunk q's staging into stage buffer (cp.async x4 + commit);
// performs the segment dependency wait when q is a segment head.
__device__ __forceinline__ void issue_chunk(int role, int q, int t, int tid,
                                            uint32_t abase) {
    const bf16 *shi, *slo;
    int rs, col0;
    if (role == 0) {
        if (q < 4) {
            shi = g_xhi + (size_t)t * B_ * C_;
            slo = g_xlo + (size_t)t * B_ * C_;
            rs = C_; col0 = q * 64;
        } else {
            if (q == 4) wait_bars(g_bars0, tid, t * 8);
            if (t == 0) { shi = g_h00hi; slo = g_h00lo; }
            else {
                shi = g_y0hi + (size_t)(t - 1) * B_ * H_;
                slo = g_y0lo + (size_t)(t - 1) * B_ * H_;
            }
            rs = H_; col0 = (q - 4) * 64;
        }
    } else {
        if (q < 8) {
            if (q == 0) wait_bars(g_bars1, tid, t * 8);
            if (t == 0) { shi = g_h01hi; slo = g_h01lo; }
            else {
                shi = g_h1hi + (size_t)(t - 1) * B_ * H_;
                slo = g_h1lo + (size_t)(t - 1) * B_ * H_;
            }
            rs = H_; col0 = q * 64;
        } else {
            if (q == 8) wait_bars(g_bars0, tid, (t + 1) * 8);
            shi = g_y0hi + (size_t)t * B_ * H_;
            slo = g_y0lo + (size_t)t * B_ * H_;
            rs = H_; col0 = (q - 8) * 64;
        }
    }
    #pragma unroll
    for (int it = 0; it < 4; it++) {
        const int seg = it * NTHR_ + tid;
        const int row = seg >> 3, s8 = seg & 7;
        const bf16* src = (row < 64 ? shi + (size_t)row * rs
                                    : slo + (size_t)(row - 64) * rs) + col0 + s8 * 8;
        const uint32_t bo = (uint32_t)(row * 128 + s8 * 16);
        const uint32_t sw = bo ^ ((bo >> 3) & 0x70);
        cp16(abase + sw, src);
    }
    cp_commit();
}

__global__ void __launch_bounds__(NTHR_, 1) lstm_kernel(
    const float* __restrict__ x,
    const float* __restrict__ h00, const float* __restrict__ c00,
    const float* __restrict__ h01, const float* __restrict__ c01,
    const float* __restrict__ Wih0, const float* __restrict__ Whh0,
    const float* __restrict__ bih0, const float* __restrict__ bhh0,
    const float* __restrict__ Wih1, const float* __restrict__ Whh1,
    const float* __restrict__ bih1, const float* __restrict__ bhh1,
    float* out)
{
    const int tid  = threadIdx.x;
    const int wid  = tid >> 5;
    const int lid  = tid & 31;
    const int bid  = blockIdx.x;
    const int role = bid >> 6;            // 0: layer0, 1: layer1
    const int j0   = (bid & 63) * 8;
    const int grp  = (bid & 63) >> 3;

    const uint32_t sb = smem_u32(smem8);
    const uint32_t sbA = sb + OFF_A;
    float* Bs = (float*)(smem8 + OFF_BS);
    float* Gr = (float*)(smem8 + OFF_GR);   // [64][33]

    const int KX = role ? H_ : C_;
    const int K  = KX + H_;
    const float* Wx    = role ? Wih1 : Wih0;
    const float* Wh    = role ? Whh1 : Whh0;
    const float* bi    = role ? bih1 : bih0;
    const float* bh    = role ? bhh1 : bhh0;
    const float* cinit = role ? c01 : c00;

    // ---- one-time: split weights into SW128 chunk tiles (hi, lo) ----
    for (int idx = tid; idx < 32 * K; idx += NTHR_) {
        const int n = idx / K, k = idx - n * K;
        const int gr = (n >> 3) * H_ + j0 + (n & 7);
        const float v = (k < KX) ? Wx[(size_t)gr * KX + k]
                                 : Wh[(size_t)gr * H_ + (k - KX)];
        const bf16 hb = __float2bfloat16(v);
        const bf16 lb = __float2bfloat16(v - __bfloat162float(hb));
        const int wc = k >> 6, kk = k & 63;
        const uint32_t bo = n * 128 + kk * 2;
        const uint32_t sw = bo ^ ((bo >> 3) & 0x70);
        *(bf16*)(smem8 + OFF_WH + wc * 4096 + sw) = hb;
        *(bf16*)(smem8 + OFF_WL + wc * 4096 + sw) = lb;
    }
    if (tid < 32) {
        const int gr = (tid >> 3) * H_ + j0 + (tid & 7);
        Bs[tid] = bi[gr] + bh[gr];
    }
    // per-thread cells: m = tid&63, gates jp..jp+1
    const int mcell = tid & 63;
    const int jp = (tid >> 6) * 2;
    float creg[2];
    creg[0] = cinit[(size_t)mcell * H_ + j0 + jp];
    creg[1] = cinit[(size_t)mcell * H_ + j0 + jp + 1];
    __syncthreads();

    // warp decomposition: 4 m-slabs x 2 n-slabs
    const int mw = wid & 3;
    const int nw = wid >> 2;
    const int jA = lid >> 3, rA = lid & 7;
    const int rowA  = ((jA & 1) << 3) + rA;
    const int colA2 = (jA >> 1) << 4;
    const uint32_t swA = (uint32_t)rA << 4;
    const int jB = (lid >> 3) & 1, rB = lid & 7;
    const int colB2 = jB << 4;
    const uint32_t swB = (uint32_t)rB << 4;
    const uint32_t aHiBase = (uint32_t)(16 * mw + rowA) * 128;
    const uint32_t aLoBase = (uint32_t)(64 + 16 * mw + rowA) * 128;
    // merged W x4: lanes 0-15 -> n-tile0, lanes 16-31 -> n-tile1
    const uint32_t bRowSel = (uint32_t)(16 * nw + ((lid & 16) ? 8 : 0) + rB) * 128;

    float* yout = out;
    float* h1f  = out + (size_t)T_ * B_ * H_;
    float* c1f  = h1f + B_ * H_;
    float* h2f  = c1f + B_ * H_;
    float* c2f  = h2f + B_ * H_;
    float* hTd  = role ? h2f : h1f;
    float* cTd  = role ? c2f : c1f;
    int* actr   = (role ? g_bars1 : g_bars0) + grp * 32;

    const int NCH = role ? 16 : 12;

    for (int t = 0; t < T_; t++) {
        float acc[2][2][4];
        #pragma unroll
        for (int i = 0; i < 2; i++)
            #pragma unroll
            for (int j = 0; j < 2; j++)
                #pragma unroll
                for (int q = 0; q < 4; q++) acc[i][j][q] = 0.0f;

        // ---- pipeline prologue: issue chunks 0..2 ----
        issue_chunk(role, 0, t, tid, sbA + 0 * 16384);
        issue_chunk(role, 1, t, tid, sbA + 1 * 16384);
        issue_chunk(role, 2, t, tid, sbA + 2 * 16384);

        #pragma unroll 1
        for (int q = 0; q < NCH; q++) {
            // drain until chunk q's group is complete
            if (q >= NCH - 1) cp_wait<0>();
            else if (q >= NCH - 2) cp_wait<1>();
            else cp_wait<2>();
            __syncthreads();              // all threads' copies visible

            // ---- compute chunk q from stage q&3 ----
            {
                const int wcc = (role == 0) ? q : (q < 8 ? 8 + q : q - 8);
                const uint32_t aBase = sbA + (uint32_t)(q & 3) * 16384;
                const uint32_t whB   = sb + OFF_WH + (uint32_t)wcc * 4096;
                const uint32_t wlB   = sb + OFF_WL + (uint32_t)wcc * 4096;
                #pragma unroll
                for (int ks = 0; ks < 4; ks++) {
                    const uint32_t kA = (uint32_t)((ks * 32 + colA2) ^ (int)swA);
                    const uint32_t kB = (uint32_t)((ks * 32 + colB2) ^ (int)swB);
                    uint32_t ah[4], al[4], bhv[4], blv[4];
                    ldsm4(aBase + aHiBase + kA, ah);
                    ldsm4(aBase + aLoBase + kA, al);
                    ldsm4(whB + bRowSel + kB, bhv);
                    ldsm4(wlB + bRowSel + kB, blv);
                    mma16816(acc[0][0], ah, bhv);
                    mma16816(acc[0][1], ah, bhv + 2);
                    mma16816(acc[1][0], al, bhv);
                    mma16816(acc[1][1], al, bhv + 2);
                    mma16816(acc[0][0], ah, blv);      // 3-product: skip lo x lo
                    mma16816(acc[0][1], ah, blv + 2);
                }
            }
            if (q + 3 < NCH)
                issue_chunk(role, q + 3, t, tid, sbA + (uint32_t)((q + 3) & 3) * 16384);
        }
        __syncthreads();

        // ---- fold hi+lo m-tiles, write gates to Gr[64][33] ----
        {
            const int mrow = 16 * mw + (lid >> 2);
            const int col0w = 16 * nw + 2 * (lid & 3);
            #pragma unroll
            for (int nt = 0; nt < 2; nt++) {
                const int cc = col0w + nt * 8;
                Gr[mrow * 33 + cc]           = acc[0][nt][0] + acc[1][nt][0];
                Gr[mrow * 33 + cc + 1]       = acc[0][nt][1] + acc[1][nt][1];
                Gr[(mrow + 8) * 33 + cc]     = acc[0][nt][2] + acc[1][nt][2];
                Gr[(mrow + 8) * 33 + cc + 1] = acc[0][nt][3] + acc[1][nt][3];
            }
        }
        __syncthreads();

        // ---- pointwise (256 threads, 2 cells each) ----
        {
            const int m = mcell;
            float hv[2];
            #pragma unroll
            for (int u = 0; u < 2; u++) {
                const int jj = jp + u;
                float gi = Gr[m * 33 + jj]      + Bs[jj];
                float gf = Gr[m * 33 + 8 + jj]  + Bs[8 + jj];
                float gg = Gr[m * 33 + 16 + jj] + Bs[16 + jj];
                float go = Gr[m * 33 + 24 + jj] + Bs[24 + jj];
                gi = sigf(gi); gf = sigf(gf); gg = tanhe(gg); go = sigf(go);
                const float cv = gf * creg[u] + gi * gg;
                creg[u] = cv;
                hv[u] = go * tanhe(cv);
            }
            const bf16 b0 = __float2bfloat16(hv[0]);
            const bf16 b1 = __float2bfloat16(hv[1]);
            const uint32_t phh = (uint32_t)__bfloat16_as_ushort(b0) |
                                 ((uint32_t)__bfloat16_as_ushort(b1) << 16);
            const bf16 l0 = __float2bfloat16(hv[0] - __bfloat162float(b0));
            const bf16 l1 = __float2bfloat16(hv[1] - __bfloat162float(b1));
            const uint32_t pll = (uint32_t)__bfloat16_as_ushort(l0) |
                                 ((uint32_t)__bfloat16_as_ushort(l1) << 16);
            const size_t off = (size_t)t * B_ * H_ + (size_t)m * H_ + j0 + jp;
            *(uint32_t*)((role ? g_h1hi : g_y0hi) + off) = phh;
            *(uint32_t*)((role ? g_h1lo : g_y0lo) + off) = pll;
            if (role)
                *(float2*)(yout + off) = make_float2(hv[0], hv[1]);
            if (t == T_ - 1) {
                const size_t foff = (size_t)m * H_ + j0 + jp;
                *(float2*)(hTd + foff) = make_float2(hv[0], hv[1]);
                *(float2*)(cTd + foff) = make_float2(creg[0], creg[1]);
            }
            __threadfence();   // order h stores before the doorbell
        }
        __syncthreads();
        if (tid == 0) atomicAdd(actr, 1);
    }
}

extern "C" void kernel_launch(void* const* d_in, const int* in_sizes, int n_in,
                              void* d_out, int out_size) {
    (void)in_sizes; (void)n_in; (void)out_size;
    cudaFuncSetAttribute(lstm_kernel, cudaFuncAttributeMaxDynamicSharedMemorySize,
                         SMEM_BYTES);
    prep_kernel<<<1024, 256>>>((const float*)d_in[0], (const float*)d_in[1],
                               (const float*)d_in[3]);
    lstm_kernel<<<GRID_, NTHR_, SMEM_BYTES>>>(
        (const float*)d_in[0],
        (const float*)d_in[1], (const float*)d_in[2],
        (const float*)d_in[3], (const float*)d_in[4],
        (const float*)d_in[5], (const float*)d_in[6],
        (const float*)d_in[7], (const float*)d_in[8],
        (const float*)d_in[9], (const float*)d_in[10],
        (const float*)d_in[11], (const float*)d_in[12],
        (float*)d_out);
}

// round 13
// speedup vs baseline: 1.2934x; 1.0485x over previous
#include <cuda_runtime.h>
#include <cuda_bf16.h>
#include <cstdint>
#include <cstddef>

// MultiLayerLSTM via mma.sync (bf16 m16n8k16), fp32 bf16 3-product split.
// A' = [batch-hi(64); batch-lo(64)] (M=128), N=32 gate rows/CTA, 256 thr.
// cp.async 4-stage ring pipelined ACROSS steps; layer1 computes its y0
// segment first (layer0 runs ahead -> never blocks) and its own-h segment
// second (peer wait hidden behind y0 compute). Single release doorbell.

#define T_ 1024
#define B_ 64
#define C_ 256
#define H_ 512
#define NTHR_ 256
#define GRID_ 128

// ---- shared memory byte offsets ----
#define OFF_BS  0                  // 32 float biases
#define OFF_GR  128                // 64 x 33 float gate matrix
#define OFF_A   9216               // 4 x 16KB A' stage ring (SW128)
#define OFF_WH  74752              // 16 x 4KB Whi chunk tiles
#define OFF_WL  140288             // 16 x 4KB Wlo chunk tiles
#define SMEM_BYTES 205824

typedef __nv_bfloat16 bf16;

static __device__ __align__(256) bf16 g_xhi[(size_t)T_ * B_ * C_];
static __device__ __align__(256) bf16 g_xlo[(size_t)T_ * B_ * C_];
static __device__ __align__(256) bf16 g_y0hi[(size_t)T_ * B_ * H_];
static __device__ __align__(256) bf16 g_y0lo[(size_t)T_ * B_ * H_];
static __device__ __align__(256) bf16 g_h1hi[(size_t)T_ * B_ * H_];
static __device__ __align__(256) bf16 g_h1lo[(size_t)T_ * B_ * H_];
static __device__ __align__(256) bf16 g_h00hi[B_ * H_], g_h00lo[B_ * H_];
static __device__ __align__(256) bf16 g_h01hi[B_ * H_], g_h01lo[B_ * H_];
static __device__ int g_bars0[8 * 32];
static __device__ int g_bars1[8 * 32];

__global__ void prep_kernel(const float* __restrict__ x,
                            const float* __restrict__ h00,
                            const float* __restrict__ h01) {
    const size_t stride = (size_t)gridDim.x * blockDim.x;
    const size_t i0 = (size_t)blockIdx.x * blockDim.x + threadIdx.x;
    const size_t nx = (size_t)T_ * B_ * C_;
    for (size_t p = i0; p < nx; p += stride) {
        float v = x[p];
        bf16 h = __float2bfloat16(v);
        g_xhi[p] = h;
        g_xlo[p] = __float2bfloat16(v - __bfloat162float(h));
    }
    for (size_t p = i0; p < (size_t)B_ * H_; p += stride) {
        float v = h00[p];
        bf16 h = __float2bfloat16(v);
        g_h00hi[p] = h;
        g_h00lo[p] = __float2bfloat16(v - __bfloat162float(h));
        v = h01[p];
        h = __float2bfloat16(v);
        g_h01hi[p] = h;
        g_h01lo[p] = __float2bfloat16(v - __bfloat162float(h));
    }
    if (blockIdx.x == 0 && threadIdx.x < 8) {
        g_bars0[threadIdx.x * 32] = 0;
        g_bars1[threadIdx.x * 32] = 0;
    }
}

__device__ __forceinline__ uint32_t smem_u32(const void* p) {
    uint32_t a;
    asm("{ .reg .u64 t; cvta.to.shared.u64 t, %1; cvt.u32.u64 %0, t; }"
        : "=r"(a) : "l"(p));
    return a;
}
__device__ __forceinline__ void cp16(uint32_t daddr, const void* gptr) {
    asm volatile("cp.async.cg.shared.global [%0], [%1], 16;"
                 :: "r"(daddr), "l"(gptr) : "memory");
}
__device__ __forceinline__ void cp_commit() {
    asm volatile("cp.async.commit_group;" ::: "memory");
}
template <int N> __device__ __forceinline__ void cp_wait() {
    asm volatile("cp.async.wait_group %0;" :: "n"(N) : "memory");
}
__device__ __forceinline__ void red_rel(int* p) {
    asm volatile(
        "{ .reg .u64 a; cvta.to.global.u64 a, %1; "
        "red.release.gpu.global.add.u32 [a], %0; }"
        :: "r"(1), "l"(p) : "memory");
}
__device__ __forceinline__ void ldsm4(uint32_t addr, uint32_t* r) {
    asm volatile("ldmatrix.sync.aligned.m8n8.x4.shared.b16 {%0,%1,%2,%3}, [%4];"
                 : "=r"(r[0]), "=r"(r[1]), "=r"(r[2]), "=r"(r[3]) : "r"(addr));
}
__device__ __forceinline__ void mma16816(float* c, const uint32_t* a,
                                         const uint32_t* b) {
    asm volatile(
        "mma.sync.aligned.m16n8k16.row.col.f32.bf16.bf16.f32 "
        "{%0,%1,%2,%3}, {%4,%5,%6,%7}, {%8,%9}, {%0,%1,%2,%3};"
        : "+f"(c[0]), "+f"(c[1]), "+f"(c[2]), "+f"(c[3])
        : "r"(a[0]), "r"(a[1]), "r"(a[2]), "r"(a[3]), "r"(b[0]), "r"(b[1]));
}
__device__ __forceinline__ float sigf(float v) { return 1.0f / (1.0f + __expf(-v)); }
__device__ __forceinline__ float tanhe(float v) {
    const float e = __expf(2.0f * v);
    return 1.0f - 2.0f / (e + 1.0f);
}

__device__ __forceinline__ void wait_bars(const int* bars, int tid, int target) {
    if (tid < 8) {
        volatile const int* p = bars + tid * 32;
        while (*p < target) { }
        __threadfence();
    }
    __syncthreads();
}

extern __shared__ char smem8[];

// issue chunk q of step t into its stage buffer (cp.async x4 + commit);
// performs the segment dependency wait when q is a segment head.
// ordering: role0 = [x(0..3) | own-h(4..11)], role1 = [y0(0..7) | own-h(8..15)]
// -> weight tile index is q for both roles.
__device__ __forceinline__ void issue_chunk(int role, int q, int t, int tid,
                                            uint32_t abase) {
    const bf16 *shi, *slo;
    int rs, col0;
    if (role == 0) {
        if (q < 4) {                          // x part, no dependency
            shi = g_xhi + (size_t)t * B_ * C_;
            slo = g_xlo + (size_t)t * B_ * C_;
            rs = C_; col0 = q * 64;
        } else {                              // own h part
            if (q == 4) wait_bars(g_bars0, tid, t * 8);
            if (t == 0) { shi = g_h00hi; slo = g_h00lo; }
            else {
                shi = g_y0hi + (size_t)(t - 1) * B_ * H_;
                slo = g_y0lo + (size_t)(t - 1) * B_ * H_;
            }
            rs = H_; col0 = (q - 4) * 64;
        }
    } else {
        if (q < 8) {                          // y0 part (layer0 step t output)
            if (q == 0) wait_bars(g_bars0, tid, (t + 1) * 8);
            shi = g_y0hi + (size_t)t * B_ * H_;
            slo = g_y0lo + (size_t)t * B_ * H_;
            rs = H_; col0 = q * 64;
        } else {                              // own h part
            if (q == 8) wait_bars(g_bars1, tid, t * 8);
            if (t == 0) { shi = g_h01hi; slo = g_h01lo; }
            else {
                shi = g_h1hi + (size_t)(t - 1) * B_ * H_;
                slo = g_h1lo + (size_t)(t - 1) * B_ * H_;
            }
            rs = H_; col0 = (q - 8) * 64;
        }
    }
    #pragma unroll
    for (int it = 0; it < 4; it++) {
        const int seg = it * NTHR_ + tid;
        const int row = seg >> 3, s8 = seg & 7;
        const bf16* src = (row < 64 ? shi + (size_t)row * rs
                                    : slo + (size_t)(row - 64) * rs) + col0 + s8 * 8;
        const uint32_t bo = (uint32_t)(row * 128 + s8 * 16);
        const uint32_t sw = bo ^ ((bo >> 3) & 0x70);
        cp16(abase + sw, src);
    }
    cp_commit();
}

__global__ void __launch_bounds__(NTHR_, 1) lstm_kernel(
    const float* __restrict__ x,
    const float* __restrict__ h00, const float* __restrict__ c00,
    const float* __restrict__ h01, const float* __restrict__ c01,
    const float* __restrict__ Wih0, const float* __restrict__ Whh0,
    const float* __restrict__ bih0, const float* __restrict__ bhh0,
    const float* __restrict__ Wih1, const float* __restrict__ Whh1,
    const float* __restrict__ bih1, const float* __restrict__ bhh1,
    float* out)
{
    const int tid  = threadIdx.x;
    const int wid  = tid >> 5;
    const int lid  = tid & 31;
    const int bid  = blockIdx.x;
    const int role = bid >> 6;            // 0: layer0, 1: layer1
    const int j0   = (bid & 63) * 8;
    const int grp  = (bid & 63) >> 3;

    const uint32_t sb = smem_u32(smem8);
    const uint32_t sbA = sb + OFF_A;
    float* Bs = (float*)(smem8 + OFF_BS);
    float* Gr = (float*)(smem8 + OFF_GR);   // [64][33]

    const int KX = role ? H_ : C_;
    const int K  = KX + H_;
    const float* Wx    = role ? Wih1 : Wih0;
    const float* Wh    = role ? Whh1 : Whh0;
    const float* bi    = role ? bih1 : bih0;
    const float* bh    = role ? bhh1 : bhh0;
    const float* cinit = role ? c01 : c00;

    // ---- one-time: split weights into SW128 chunk tiles (hi, lo) ----
    for (int idx = tid; idx < 32 * K; idx += NTHR_) {
        const int n = idx / K, k = idx - n * K;
        const int gr = (n >> 3) * H_ + j0 + (n & 7);
        const float v = (k < KX) ? Wx[(size_t)gr * KX + k]
                                 : Wh[(size_t)gr * H_ + (k - KX)];
        const bf16 hb = __float2bfloat16(v);
        const bf16 lb = __float2bfloat16(v - __bfloat162float(hb));
        const int wc = k >> 6, kk = k & 63;
        const uint32_t bo = n * 128 + kk * 2;
        const uint32_t sw = bo ^ ((bo >> 3) & 0x70);
        *(bf16*)(smem8 + OFF_WH + wc * 4096 + sw) = hb;
        *(bf16*)(smem8 + OFF_WL + wc * 4096 + sw) = lb;
    }
    if (tid < 32) {
        const int gr = (tid >> 3) * H_ + j0 + (tid & 7);
        Bs[tid] = bi[gr] + bh[gr];
    }
    // per-thread cells: m = tid&63, gates jp..jp+1
    const int mcell = tid & 63;
    const int jp = (tid >> 6) * 2;
    float creg[2];
    creg[0] = cinit[(size_t)mcell * H_ + j0 + jp];
    creg[1] = cinit[(size_t)mcell * H_ + j0 + jp + 1];
    __syncthreads();

    // warp decomposition: 4 m-slabs x 2 n-slabs
    const int mw = wid & 3;
    const int nw = wid >> 2;
    const int jA = lid >> 3, rA = lid & 7;
    const int rowA  = ((jA & 1) << 3) + rA;
    const int colA2 = (jA >> 1) << 4;
    const uint32_t swA = (uint32_t)rA << 4;
    const int rB = lid & 7;
    const int colB2 = ((lid >> 3) & 1) << 4;
    const uint32_t swB = (uint32_t)rB << 4;
    const uint32_t aHiBase = (uint32_t)(16 * mw + rowA) * 128;
    const uint32_t aLoBase = (uint32_t)(64 + 16 * mw + rowA) * 128;
    // merged W x4: lanes 0-15 -> n-tile0, lanes 16-31 -> n-tile1
    const uint32_t bRowSel = (uint32_t)(16 * nw + ((lid & 16) ? 8 : 0) + rB) * 128;

    float* yout = out;
    float* h1f  = out + (size_t)T_ * B_ * H_;
    float* c1f  = h1f + B_ * H_;
    float* h2f  = c1f + B_ * H_;
    float* c2f  = h2f + B_ * H_;
    float* hTd  = role ? h2f : h1f;
    float* cTd  = role ? c2f : c1f;
    int* actr   = (role ? g_bars1 : g_bars0) + grp * 32;

    const int NCH = role ? 16 : 12;

    // ---- pipeline prologue: chunks 0..2 of step 0 ----
    issue_chunk(role, 0, 0, tid, sbA + 0 * 16384);
    issue_chunk(role, 1, 0, tid, sbA + 1 * 16384);
    issue_chunk(role, 2, 0, tid, sbA + 2 * 16384);

    for (int t = 0; t < T_; t++) {
        float acc[2][2][4];
        #pragma unroll
        for (int i = 0; i < 2; i++)
            #pragma unroll
            for (int j = 0; j < 2; j++)
                #pragma unroll
                for (int q = 0; q < 4; q++) acc[i][j][q] = 0.0f;

        #pragma unroll 1
        for (int q = 0; q < NCH; q++) {
            // drain until chunk q's group is complete
            if (t == T_ - 1 && q >= NCH - 2) {
                if (q == NCH - 1) cp_wait<0>();
                else cp_wait<1>();
            } else {
                cp_wait<2>();
            }
            __syncthreads();              // all threads' copies visible

            // ---- compute chunk q from stage q&3 (weight tile = q) ----
            {
                const uint32_t aBase = sbA + (uint32_t)(q & 3) * 16384;
                const uint32_t whB   = sb + OFF_WH + (uint32_t)q * 4096;
                const uint32_t wlB   = sb + OFF_WL + (uint32_t)q * 4096;
                #pragma unroll
                for (int ks = 0; ks < 4; ks++) {
                    const uint32_t kA = (uint32_t)((ks * 32 + colA2) ^ (int)swA);
                    const uint32_t kB = (uint32_t)((ks * 32 + colB2) ^ (int)swB);
                    uint32_t ah[4], al[4], bhv[4], blv[4];
                    ldsm4(aBase + aHiBase + kA, ah);
                    ldsm4(aBase + aLoBase + kA, al);
                    ldsm4(whB + bRowSel + kB, bhv);
                    ldsm4(wlB + bRowSel + kB, blv);
                    mma16816(acc[0][0], ah, bhv);
                    mma16816(acc[0][1], ah, bhv + 2);
                    mma16816(acc[1][0], al, bhv);
                    mma16816(acc[1][1], al, bhv + 2);
                    mma16816(acc[0][0], ah, blv);      // 3-product: skip lo x lo
                    mma16816(acc[0][1], ah, blv + 2);
                }
            }
            // issue 3 chunks ahead; roll over into the next step's head
            const int nq = q + 3;
            if (nq < NCH)
                issue_chunk(role, nq, t, tid, sbA + (uint32_t)(nq & 3) * 16384);
            else if (t + 1 < T_)
                issue_chunk(role, nq - NCH, t + 1, tid,
                            sbA + (uint32_t)((nq - NCH) & 3) * 16384);
        }

        // ---- fold hi+lo m-tiles, write gates to Gr[64][33] ----
        {
            const int mrow = 16 * mw + (lid >> 2);
            const int col0w = 16 * nw + 2 * (lid & 3);
            #pragma unroll
            for (int nt = 0; nt < 2; nt++) {
                const int cc = col0w + nt * 8;
                Gr[mrow * 33 + cc]           = acc[0][nt][0] + acc[1][nt][0];
                Gr[mrow * 33 + cc + 1]       = acc[0][nt][1] + acc[1][nt][1];
                Gr[(mrow + 8) * 33 + cc]     = acc[0][nt][2] + acc[1][nt][2];
                Gr[(mrow + 8) * 33 + cc + 1] = acc[0][nt][3] + acc[1][nt][3];
            }
        }
        __syncthreads();

        // ---- pointwise (256 threads, 2 cells each) ----
        {
            const int m = mcell;
            float hv[2];
            #pragma unroll
            for (int u = 0; u < 2; u++) {
                const int jj = jp + u;
                float gi = Gr[m * 33 + jj]      + Bs[jj];
                float gf = Gr[m * 33 + 8 + jj]  + Bs[8 + jj];
                float gg = Gr[m * 33 + 16 + jj] + Bs[16 + jj];
                float go = Gr[m * 33 + 24 + jj] + Bs[24 + jj];
                gi = sigf(gi); gf = sigf(gf); gg = tanhe(gg); go = sigf(go);
                const float cv = gf * creg[u] + gi * gg;
                creg[u] = cv;
                hv[u] = go * tanhe(cv);
            }
            const bf16 b0 = __float2bfloat16(hv[0]);
            const bf16 b1 = __float2bfloat16(hv[1]);
            const uint32_t phh = (uint32_t)__bfloat16_as_ushort(b0) |
                                 ((uint32_t)__bfloat16_as_ushort(b1) << 16);
            const bf16 l0 = __float2bfloat16(hv[0] - __bfloat162float(b0));
            const bf16 l1 = __float2bfloat16(hv[1] - __bfloat162float(b1));
            const uint32_t pll = (uint32_t)__bfloat16_as_ushort(l0) |
                                 ((uint32_t)__bfloat16_as_ushort(l1) << 16);
            const size_t off = (size_t)t * B_ * H_ + (size_t)m * H_ + j0 + jp;
            *(uint32_t*)((role ? g_h1hi : g_y0hi) + off) = phh;
            *(uint32_t*)((role ? g_h1lo : g_y0lo) + off) = pll;
            if (role)
                *(float2*)(yout + off) = make_float2(hv[0], hv[1]);
            if (t == T_ - 1) {
                const size_t foff = (size_t)m * H_ + j0 + jp;
                *(float2*)(hTd + foff) = make_float2(hv[0], hv[1]);
                *(float2*)(cTd + foff) = make_float2(creg[0], creg[1]);
            }
        }
        __syncthreads();
        // release doorbell: bar.sync orders all threads' h stores before it
        if (tid == 0) red_rel(actr);
    }
}

extern "C" void kernel_launch(void* const* d_in, const int* in_sizes, int n_in,
                              void* d_out, int out_size) {
    (void)in_sizes; (void)n_in; (void)out_size;
    cudaFuncSetAttribute(lstm_kernel, cudaFuncAttributeMaxDynamicSharedMemorySize,
                         SMEM_BYTES);
    prep_kernel<<<1024, 256>>>((const float*)d_in[0], (const float*)d_in[1],
                               (const float*)d_in[3]);
    lstm_kernel<<<GRID_, NTHR_, SMEM_BYTES>>>(
        (const float*)d_in[0],
        (const float*)d_in[1], (const float*)d_in[2],
        (const float*)d_in[3], (const float*)d_in[4],
        (const float*)d_in[5], (const float*)d_in[6],
        (const float*)d_in[7], (const float*)d_in[8],
        (const float*)d_in[9], (const float*)d_in[10],
        (const float*)d_in[11], (const float*)d_in[12],
        (float*)d_out);
}

// round 14
// speedup vs baseline: 1.5414x; 1.1918x over previous
#include <cuda_runtime.h>
#include <cuda_bf16.h>
#include <cstdint>
#include <cstddef>

// MultiLayerLSTM via mma.sync (bf16 m16n8k16), fp32 bf16 3-product split.
// K-SPLIT wavefront: per layer, 32 slabs of N=64 gates; each slab has CTA-A
// (input-projection half: x/y0, no own-layer recurrence dep) and CTA-B
// (h*Whh half = 8 chunks + merge + pointwise = the recurrence loop).
// A ships fp32 partial gates via parity-buffered L2 scratch + release flag.
// Per-slab-exact doorbells (32 counters/layer).

#define T_ 1024
#define B_ 64
#define C_ 256
#define H_ 512
#define NTHR_ 256
#define GRID_ 128

// ---- shared memory byte offsets ----
#define OFF_BS  0                  // 64 float biases (B only)
#define OFF_GR  256                // 64 x 72 float gate matrix
#define OFF_A   19456              // 4 x 16KB A' stage ring (SW128)
#define OFF_WH  84992              // 8 x 8KB Whi tiles (64 rows x 64k)
#define OFF_WL  150528             // 8 x 8KB Wlo tiles
#define SMEM_BYTES 216064

typedef __nv_bfloat16 bf16;

static __device__ __align__(256) bf16 g_xhi[(size_t)T_ * B_ * C_];
static __device__ __align__(256) bf16 g_xlo[(size_t)T_ * B_ * C_];
static __device__ __align__(256) bf16 g_y0hi[(size_t)T_ * B_ * H_];
static __device__ __align__(256) bf16 g_y0lo[(size_t)T_ * B_ * H_];
static __device__ __align__(256) bf16 g_h1hi[(size_t)T_ * B_ * H_];
static __device__ __align__(256) bf16 g_h1lo[(size_t)T_ * B_ * H_];
static __device__ __align__(256) bf16 g_h00hi[B_ * H_], g_h00lo[B_ * H_];
static __device__ __align__(256) bf16 g_h01hi[B_ * H_], g_h01lo[B_ * H_];
static __device__ float g_part[2][32][2][4096];    // [layer][slab][parity][64m x 64n]
static __device__ int g_done[2][1024];             // per-slab doorbells, stride 32
static __device__ int g_aflag[2][1024];            // A->B partial flags, stride 32

__global__ void prep_kernel(const float* __restrict__ x,
                            const float* __restrict__ h00,
                            const float* __restrict__ h01) {
    const size_t stride = (size_t)gridDim.x * blockDim.x;
    const size_t i0 = (size_t)blockIdx.x * blockDim.x + threadIdx.x;
    const size_t nx = (size_t)T_ * B_ * C_;
    for (size_t p = i0; p < nx; p += stride) {
        float v = x[p];
        bf16 h = __float2bfloat16(v);
        g_xhi[p] = h;
        g_xlo[p] = __float2bfloat16(v - __bfloat162float(h));
    }
    for (size_t p = i0; p < (size_t)B_ * H_; p += stride) {
        float v = h00[p];
        bf16 h = __float2bfloat16(v);
        g_h00hi[p] = h;
        g_h00lo[p] = __float2bfloat16(v - __bfloat162float(h));
        v = h01[p];
        h = __float2bfloat16(v);
        g_h01hi[p] = h;
        g_h01lo[p] = __float2bfloat16(v - __bfloat162float(h));
    }
    for (size_t p = i0; p < 1024; p += stride) {
        g_done[0][p] = 0; g_done[1][p] = 0;
        g_aflag[0][p] = 0; g_aflag[1][p] = 0;
    }
}

__device__ __forceinline__ uint32_t smem_u32(const void* p) {
    uint32_t a;
    asm("{ .reg .u64 t; cvta.to.shared.u64 t, %1; cvt.u32.u64 %0, t; }"
        : "=r"(a) : "l"(p));
    return a;
}
__device__ __forceinline__ int ld_acq(const int* p) {
    int v;
    asm volatile(
        "{ .reg .u64 a; cvta.to.global.u64 a, %1; "
        "ld.acquire.gpu.global.b32 %0, [a]; }"
        : "=r"(v) : "l"(p) : "memory");
    return v;
}
__device__ __forceinline__ void red_rel(int* p) {
    asm volatile(
        "{ .reg .u64 a; cvta.to.global.u64 a, %1; "
        "red.release.gpu.global.add.u32 [a], %0; }"
        :: "r"(1), "l"(p) : "memory");
}
__device__ __forceinline__ void cp16(uint32_t daddr, const void* gptr) {
    asm volatile("cp.async.cg.shared.global [%0], [%1], 16;"
                 :: "r"(daddr), "l"(gptr) : "memory");
}
__device__ __forceinline__ void cp_commit() {
    asm volatile("cp.async.commit_group;" ::: "memory");
}
template <int N> __device__ __forceinline__ void cp_wait() {
    asm volatile("cp.async.wait_group %0;" :: "n"(N) : "memory");
}
__device__ __forceinline__ void ldsm4(uint32_t addr, uint32_t* r) {
    asm volatile("ldmatrix.sync.aligned.m8n8.x4.shared.b16 {%0,%1,%2,%3}, [%4];"
                 : "=r"(r[0]), "=r"(r[1]), "=r"(r[2]), "=r"(r[3]) : "r"(addr));
}
__device__ __forceinline__ void mma16816(float* c, const uint32_t* a,
                                         const uint32_t* b) {
    asm volatile(
        "mma.sync.aligned.m16n8k16.row.col.f32.bf16.bf16.f32 "
        "{%0,%1,%2,%3}, {%4,%5,%6,%7}, {%8,%9}, {%0,%1,%2,%3};"
        : "+f"(c[0]), "+f"(c[1]), "+f"(c[2]), "+f"(c[3])
        : "r"(a[0]), "r"(a[1]), "r"(a[2]), "r"(a[3]), "r"(b[0]), "r"(b[1]));
}
__device__ __forceinline__ float sigf(float v) { return 1.0f / (1.0f + __expf(-v)); }
__device__ __forceinline__ float tanhe(float v) {
    const float e = __expf(2.0f * v);
    return 1.0f - 2.0f / (e + 1.0f);
}

extern __shared__ char smem8[];

__global__ void __launch_bounds__(NTHR_, 1) lstm_kernel(
    const float* __restrict__ x,
    const float* __restrict__ h00, const float* __restrict__ c00,
    const float* __restrict__ h01, const float* __restrict__ c01,
    const float* __restrict__ Wih0, const float* __restrict__ Whh0,
    const float* __restrict__ bih0, const float* __restrict__ bhh0,
    const float* __restrict__ Wih1, const float* __restrict__ Whh1,
    const float* __restrict__ bih1, const float* __restrict__ bhh1,
    float* out)
{
    const int tid  = threadIdx.x;
    const int wid  = tid >> 5;
    const int lid  = tid & 31;
    const int bid  = blockIdx.x;
    const int role = bid >> 6;                 // layer 0 / 1
    const bool isA = ((bid >> 5) & 1) == 0;    // A: input-proj half, B: h half
    const int slab = bid & 31;                 // 32 slabs of N=64 gates
    const int j0   = slab * 16;                // hidden base of slab

    const uint32_t sb = smem_u32(smem8);
    const uint32_t sbA = sb + OFF_A;
    float* Bs = (float*)(smem8 + OFF_BS);
    float* Gr = (float*)(smem8 + OFF_GR);      // [64][72]

    const float* Wsrc = isA ? (role ? Wih1 : Wih0) : (role ? Whh1 : Whh0);
    const int KW  = isA ? (role ? 512 : 256) : 512;
    const int NCH = KW >> 6;                   // 4 or 8
    const float* bi = role ? bih1 : bih0;
    const float* bh = role ? bhh1 : bhh0;
    const float* cinit = role ? c01 : c00;

    // ---- one-time: split weight half into SW128 tiles (hi, lo) ----
    for (int idx = tid; idx < 64 * KW; idx += NTHR_) {
        const int n = idx / KW, k = idx - n * KW;
        const int grow = (n >> 4) * H_ + j0 + (n & 15);
        const float v = Wsrc[(size_t)grow * KW + k];
        const bf16 hb = __float2bfloat16(v);
        const bf16 lb = __float2bfloat16(v - __bfloat162float(hb));
        const int tile = k >> 6, kk = k & 63;
        const uint32_t bo = n * 128 + kk * 2;
        const uint32_t sw = bo ^ ((bo >> 3) & 0x70);
        *(bf16*)(smem8 + OFF_WH + tile * 8192 + sw) = hb;
        *(bf16*)(smem8 + OFF_WL + tile * 8192 + sw) = lb;
    }
    if (!isA && tid < 64) {
        const int grow = (tid >> 4) * H_ + j0 + (tid & 15);
        Bs[tid] = bi[grow] + bh[grow];
    }
    // B cells: m = tid&63, hidden jj0..jj0+3
    const int mcell = tid & 63;
    const int jj0 = (tid >> 6) * 4;
    float creg[4];
    if (!isA) {
        #pragma unroll
        for (int u = 0; u < 4; u++)
            creg[u] = cinit[(size_t)mcell * H_ + j0 + jj0 + u];
    }
    __syncthreads();

    // warp decomposition: 4 m-slabs x 2 n-halves (N=64 -> 4 n8-tiles/warp)
    const int mw = wid & 3;
    const int nw = wid >> 2;
    const int jA = lid >> 3, rA = lid & 7;
    const int rowA  = ((jA & 1) << 3) + rA;
    const int colA2 = (jA >> 1) << 4;
    const uint32_t swA = (uint32_t)rA << 4;
    const int rB = lid & 7;
    const int colB2 = ((lid >> 3) & 1) << 4;
    const uint32_t swB = (uint32_t)rB << 4;
    const uint32_t aHiBase = (uint32_t)(16 * mw + rowA) * 128;
    const uint32_t aLoBase = (uint32_t)(64 + 16 * mw + rowA) * 128;
    const uint32_t bRow0 = (uint32_t)(32 * nw + ((lid & 16) ? 8 : 0) + rB) * 128;
    const uint32_t bRow1 = bRow0 + 16 * 128;

    float* yout = out;
    float* h1f  = out + (size_t)T_ * B_ * H_;
    float* c1f  = h1f + B_ * H_;
    float* h2f  = c1f + B_ * H_;
    float* c2f  = h2f + B_ * H_;
    float* hTd  = role ? h2f : h1f;
    float* cTd  = role ? c2f : c1f;

    for (int t = 0; t < T_; t++) {
        // ---- step-head dependency waits ----
        if (isA) {
            if (role == 0) {
                if (t >= 2 && tid == 0)
                    while (ld_acq(&g_done[0][slab * 32]) < t - 1) { }
            } else {
                if (tid < 32)
                    while (ld_acq(&g_done[0][tid * 32]) < t + 1) { }
                else if (tid == 32 && t >= 2)
                    while (ld_acq(&g_done[1][slab * 32]) < t - 1) { }
            }
            __syncthreads();
        } else {
            if (t >= 1) {
                if (tid < 32)
                    while (ld_acq(&g_done[role][tid * 32]) < t) { }
                __syncthreads();
            }
        }

        // ---- resolve source (hi/lo pair) for this step ----
        const bf16 *shi, *slo;
        int rs;
        if (isA) {
            if (role == 0) {
                shi = g_xhi + (size_t)t * B_ * C_;
                slo = g_xlo + (size_t)t * B_ * C_;
                rs = C_;
            } else {
                shi = g_y0hi + (size_t)t * B_ * H_;
                slo = g_y0lo + (size_t)t * B_ * H_;
                rs = H_;
            }
        } else {
            if (t == 0) {
                shi = role ? g_h01hi : g_h00hi;
                slo = role ? g_h01lo : g_h00lo;
            } else {
                shi = (role ? g_h1hi : g_y0hi) + (size_t)(t - 1) * B_ * H_;
                slo = (role ? g_h1lo : g_y0lo) + (size_t)(t - 1) * B_ * H_;
            }
            rs = H_;
        }

        float acc[2][4][4];
        #pragma unroll
        for (int i = 0; i < 2; i++)
            #pragma unroll
            for (int j = 0; j < 4; j++)
                #pragma unroll
                for (int q = 0; q < 4; q++) acc[i][j][q] = 0.0f;

        // ---- staged chunk pipeline (ring 4, prologue 3) ----
        int issued = (NCH < 3) ? NCH : 3;
        for (int q = 0; q < issued; q++) {
            const uint32_t abase = sbA + (uint32_t)(q & 3) * 16384;
            #pragma unroll
            for (int it = 0; it < 4; it++) {
                const int seg = it * NTHR_ + tid;
                const int row = seg >> 3, s8 = seg & 7;
                const bf16* src = (row < 64 ? shi + (size_t)row * rs
                                            : slo + (size_t)(row - 64) * rs)
                                  + q * 64 + s8 * 8;
                const uint32_t bo = (uint32_t)(row * 128 + s8 * 16);
                const uint32_t sw = bo ^ ((bo >> 3) & 0x70);
                cp16(abase + sw, src);
            }
            cp_commit();
        }

        #pragma unroll 1
        for (int q = 0; q < NCH; q++) {
            const int ahead = issued - q - 1;
            if (ahead >= 2) cp_wait<2>();
            else if (ahead == 1) cp_wait<1>();
            else cp_wait<0>();
            __syncthreads();

            // ---- compute chunk q ----
            {
                const uint32_t aBase = sbA + (uint32_t)(q & 3) * 16384;
                const uint32_t whT = sb + OFF_WH + (uint32_t)q * 8192;
                const uint32_t wlT = sb + OFF_WL + (uint32_t)q * 8192;
                #pragma unroll
                for (int ks = 0; ks < 4; ks++) {
                    const uint32_t kA = (uint32_t)((ks * 32 + colA2) ^ (int)swA);
                    const uint32_t kB = (uint32_t)((ks * 32 + colB2) ^ (int)swB);
                    uint32_t ah[4], al[4], wh0[4], wh1[4], wl0[4], wl1[4];
                    ldsm4(aBase + aHiBase + kA, ah);
                    ldsm4(aBase + aLoBase + kA, al);
                    ldsm4(whT + bRow0 + kB, wh0);
                    ldsm4(whT + bRow1 + kB, wh1);
                    ldsm4(wlT + bRow0 + kB, wl0);
                    ldsm4(wlT + bRow1 + kB, wl1);
                    mma16816(acc[0][0], ah, wh0); mma16816(acc[0][1], ah, wh0 + 2);
                    mma16816(acc[0][2], ah, wh1); mma16816(acc[0][3], ah, wh1 + 2);
                    mma16816(acc[1][0], al, wh0); mma16816(acc[1][1], al, wh0 + 2);
                    mma16816(acc[1][2], al, wh1); mma16816(acc[1][3], al, wh1 + 2);
                    mma16816(acc[0][0], ah, wl0); mma16816(acc[0][1], ah, wl0 + 2);
                    mma16816(acc[0][2], ah, wl1); mma16816(acc[0][3], ah, wl1 + 2);
                }
            }
            if (issued < NCH) {
                const int nq = issued;
                const uint32_t abase = sbA + (uint32_t)(nq & 3) * 16384;
                #pragma unroll
                for (int it = 0; it < 4; it++) {
                    const int seg = it * NTHR_ + tid;
                    const int row = seg >> 3, s8 = seg & 7;
                    const bf16* src = (row < 64 ? shi + (size_t)row * rs
                                                : slo + (size_t)(row - 64) * rs)
                                      + nq * 64 + s8 * 8;
                    const uint32_t bo = (uint32_t)(row * 128 + s8 * 16);
                    const uint32_t sw = bo ^ ((bo >> 3) & 0x70);
                    cp16(abase + sw, src);
                }
                cp_commit();
                issued++;
            }
        }
        __syncthreads();

        // ---- fold hi+lo, write partial gates to Gr[64][72] ----
        {
            const int mrow = 16 * mw + (lid >> 2);
            const int cbase = 32 * nw + 2 * (lid & 3);
            #pragma unroll
            for (int nt = 0; nt < 4; nt++) {
                const int cc = cbase + nt * 8;
                Gr[mrow * 72 + cc]           = acc[0][nt][0] + acc[1][nt][0];
                Gr[mrow * 72 + cc + 1]       = acc[0][nt][1] + acc[1][nt][1];
                Gr[(mrow + 8) * 72 + cc]     = acc[0][nt][2] + acc[1][nt][2];
                Gr[(mrow + 8) * 72 + cc + 1] = acc[0][nt][3] + acc[1][nt][3];
            }
        }
        __syncthreads();

        if (isA) {
            // ---- ship partial to scratch, ring flag ----
            float* sc = &g_part[role][slab][t & 1][0];
            const int row = tid >> 2, qq = tid & 3;
            const float* gsrc = Gr + row * 72 + qq * 16;
            float4* dst = (float4*)(sc + row * 64 + qq * 16);
            dst[0] = *(const float4*)(gsrc);
            dst[1] = *(const float4*)(gsrc + 4);
            dst[2] = *(const float4*)(gsrc + 8);
            dst[3] = *(const float4*)(gsrc + 12);
            __syncthreads();
            if (tid == 0) red_rel(&g_aflag[role][slab * 32]);
        } else {
            // ---- merge A partial ----
            if (tid == 0)
                while (ld_acq(&g_aflag[role][slab * 32]) < t + 1) { }
            __syncthreads();
            {
                const float* sc = &g_part[role][slab][t & 1][0];
                const int row = tid >> 2, qq = tid & 3;
                float* g = Gr + row * 72 + qq * 16;
                const float* s = sc + row * 64 + qq * 16;
                #pragma unroll
                for (int i = 0; i < 4; i++) {
                    float4 vs = *(const float4*)(s + 4 * i);
                    float4 vg = *(const float4*)(g + 4 * i);
                    vg.x += vs.x; vg.y += vs.y; vg.z += vs.z; vg.w += vs.w;
                    *(float4*)(g + 4 * i) = vg;
                }
            }
            __syncthreads();

            // ---- pointwise: 4 cells (m, jj0..jj0+3) ----
            float hv[4];
            #pragma unroll
            for (int u = 0; u < 4; u++) {
                const int nn = jj0 + u;
                float gi = Gr[mcell * 72 + nn]      + Bs[nn];
                float gf = Gr[mcell * 72 + 16 + nn] + Bs[16 + nn];
                float gg = Gr[mcell * 72 + 32 + nn] + Bs[32 + nn];
                float go = Gr[mcell * 72 + 48 + nn] + Bs[48 + nn];
                gi = sigf(gi); gf = sigf(gf); gg = tanhe(gg); go = sigf(go);
                const float cv = gf * creg[u] + gi * gg;
                creg[u] = cv;
                hv[u] = go * tanhe(cv);
            }
            uint32_t phh[2], pll[2];
            #pragma unroll
            for (int p2 = 0; p2 < 2; p2++) {
                const float a = hv[2 * p2], b = hv[2 * p2 + 1];
                const bf16 ba = __float2bfloat16(a), bb = __float2bfloat16(b);
                phh[p2] = (uint32_t)__bfloat16_as_ushort(ba) |
                          ((uint32_t)__bfloat16_as_ushort(bb) << 16);
                const bf16 la = __float2bfloat16(a - __bfloat162float(ba));
                const bf16 lb = __float2bfloat16(b - __bfloat162float(bb));
                pll[p2] = (uint32_t)__bfloat16_as_ushort(la) |
                          ((uint32_t)__bfloat16_as_ushort(lb) << 16);
            }
            const size_t off = (size_t)t * B_ * H_ + (size_t)mcell * H_ + j0 + jj0;
            *(uint2*)((role ? g_h1hi : g_y0hi) + off) = make_uint2(phh[0], phh[1]);
            *(uint2*)((role ? g_h1lo : g_y0lo) + off) = make_uint2(pll[0], pll[1]);
            if (role)
                *(float4*)(yout + off) = make_float4(hv[0], hv[1], hv[2], hv[3]);
            if (t == T_ - 1) {
                const size_t foff = (size_t)mcell * H_ + j0 + jj0;
                *(float4*)(hTd + foff) = make_float4(hv[0], hv[1], hv[2], hv[3]);
                *(float4*)(cTd + foff) = make_float4(creg[0], creg[1], creg[2], creg[3]);
            }
            __syncthreads();
            if (tid == 0) red_rel(&g_done[role][slab * 32]);
        }
    }
}

extern "C" void kernel_launch(void* const* d_in, const int* in_sizes, int n_in,
                              void* d_out, int out_size) {
    (void)in_sizes; (void)n_in; (void)out_size;
    cudaFuncSetAttribute(lstm_kernel, cudaFuncAttributeMaxDynamicSharedMemorySize,
                         SMEM_BYTES);
    prep_kernel<<<1024, 256>>>((const float*)d_in[0], (const float*)d_in[1],
                               (const float*)d_in[3]);
    lstm_kernel<<<GRID_, NTHR_, SMEM_BYTES>>>(
        (const float*)d_in[0],
        (const float*)d_in[1], (const float*)d_in[2],
        (const float*)d_in[3], (const float*)d_in[4],
        (const float*)d_in[5], (const float*)d_in[6],
        (const float*)d_in[7], (const float*)d_in[8],
        (const float*)d_in[9], (const float*)d_in[10],
        (const float*)d_in[11], (const float*)d_in[12],
        (float*)d_out);
}

// round 15
// speedup vs baseline: 2.1621x; 1.4027x over previous
#include <cuda_runtime.h>
#include <cuda_fp16.h>
#include <cstdint>
#include <cstddef>

// MultiLayerLSTM via mma.sync m16n8k16.f32.f16.f16.f32 (single-product fp16).
// K-SPLIT wavefront (R14 structure): per layer, 32 slabs of N=64 gates;
// CTA-A = input-projection half (x / y0), CTA-B = h*Whh half (8 chunks) +
// merge + pointwise (the recurrence loop). fp32 partial scratch with parity
// buffers + release flags; per-slab doorbells. M=64 (batch only) — no hi/lo.

#define T_ 1024
#define B_ 64
#define C_ 256
#define H_ 512
#define NTHR_ 256
#define GRID_ 128

// ---- shared memory byte offsets ----
#define OFF_BS  0                  // 64 float biases (B only)
#define OFF_GR  256                // 64 x 72 float gate matrix
#define OFF_A   18944              // 4 x 8KB A stage ring (SW128, 64 rows)
#define OFF_WH  51712              // 8 x 8KB W fp16 tiles (64 rows x 64k)
#define SMEM_BYTES 117248

typedef __half fp16;

static __device__ __align__(256) fp16 g_x16[(size_t)T_ * B_ * C_];
static __device__ __align__(256) fp16 g_y016[(size_t)T_ * B_ * H_];
static __device__ __align__(256) fp16 g_h116[(size_t)T_ * B_ * H_];
static __device__ __align__(256) fp16 g_h0016[B_ * H_], g_h0116[B_ * H_];
static __device__ float g_part[2][32][2][4096];    // [layer][slab][parity][64m x 64n]
static __device__ int g_done[2][1024];             // per-slab doorbells, stride 32
static __device__ int g_aflag[2][1024];            // A->B partial flags, stride 32

__global__ void prep_kernel(const float* __restrict__ x,
                            const float* __restrict__ h00,
                            const float* __restrict__ h01) {
    const size_t stride = (size_t)gridDim.x * blockDim.x;
    const size_t i0 = (size_t)blockIdx.x * blockDim.x + threadIdx.x;
    const size_t nx = (size_t)T_ * B_ * C_;
    for (size_t p = i0; p < nx; p += stride)
        g_x16[p] = __float2half(x[p]);
    for (size_t p = i0; p < (size_t)B_ * H_; p += stride) {
        g_h0016[p] = __float2half(h00[p]);
        g_h0116[p] = __float2half(h01[p]);
    }
    for (size_t p = i0; p < 1024; p += stride) {
        g_done[0][p] = 0; g_done[1][p] = 0;
        g_aflag[0][p] = 0; g_aflag[1][p] = 0;
    }
}

__device__ __forceinline__ uint32_t smem_u32(const void* p) {
    uint32_t a;
    asm("{ .reg .u64 t; cvta.to.shared.u64 t, %1; cvt.u32.u64 %0, t; }"
        : "=r"(a) : "l"(p));
    return a;
}
__device__ __forceinline__ int ld_acq(const int* p) {
    int v;
    asm volatile(
        "{ .reg .u64 a; cvta.to.global.u64 a, %1; "
        "ld.acquire.gpu.global.b32 %0, [a]; }"
        : "=r"(v) : "l"(p) : "memory");
    return v;
}
__device__ __forceinline__ void red_rel(int* p) {
    asm volatile(
        "{ .reg .u64 a; cvta.to.global.u64 a, %1; "
        "red.release.gpu.global.add.u32 [a], %0; }"
        :: "r"(1), "l"(p) : "memory");
}
__device__ __forceinline__ void cp16(uint32_t daddr, const void* gptr) {
    asm volatile("cp.async.cg.shared.global [%0], [%1], 16;"
                 :: "r"(daddr), "l"(gptr) : "memory");
}
__device__ __forceinline__ void cp_commit() {
    asm volatile("cp.async.commit_group;" ::: "memory");
}
template <int N> __device__ __forceinline__ void cp_wait() {
    asm volatile("cp.async.wait_group %0;" :: "n"(N) : "memory");
}
__device__ __forceinline__ void ldsm4(uint32_t addr, uint32_t* r) {
    asm volatile("ldmatrix.sync.aligned.m8n8.x4.shared.b16 {%0,%1,%2,%3}, [%4];"
                 : "=r"(r[0]), "=r"(r[1]), "=r"(r[2]), "=r"(r[3]) : "r"(addr));
}
__device__ __forceinline__ void mma16816h(float* c, const uint32_t* a,
                                          const uint32_t* b) {
    asm volatile(
        "mma.sync.aligned.m16n8k16.row.col.f32.f16.f16.f32 "
        "{%0,%1,%2,%3}, {%4,%5,%6,%7}, {%8,%9}, {%0,%1,%2,%3};"
        : "+f"(c[0]), "+f"(c[1]), "+f"(c[2]), "+f"(c[3])
        : "r"(a[0]), "r"(a[1]), "r"(a[2]), "r"(a[3]), "r"(b[0]), "r"(b[1]));
}
__device__ __forceinline__ float sigf(float v) { return 1.0f / (1.0f + __expf(-v)); }
__device__ __forceinline__ float tanhe(float v) {
    const float e = __expf(2.0f * v);
    return 1.0f - 2.0f / (e + 1.0f);
}

extern __shared__ char smem8[];

__global__ void __launch_bounds__(NTHR_, 1) lstm_kernel(
    const float* __restrict__ x,
    const float* __restrict__ h00, const float* __restrict__ c00,
    const float* __restrict__ h01, const float* __restrict__ c01,
    const float* __restrict__ Wih0, const float* __restrict__ Whh0,
    const float* __restrict__ bih0, const float* __restrict__ bhh0,
    const float* __restrict__ Wih1, const float* __restrict__ Whh1,
    const float* __restrict__ bih1, const float* __restrict__ bhh1,
    float* out)
{
    const int tid  = threadIdx.x;
    const int wid  = tid >> 5;
    const int lid  = tid & 31;
    const int bid  = blockIdx.x;
    const int role = bid >> 6;                 // layer 0 / 1
    const bool isA = ((bid >> 5) & 1) == 0;    // A: input-proj half, B: h half
    const int slab = bid & 31;                 // 32 slabs of N=64 gates
    const int j0   = slab * 16;                // hidden base of slab

    const uint32_t sb = smem_u32(smem8);
    const uint32_t sbA = sb + OFF_A;
    float* Bs = (float*)(smem8 + OFF_BS);
    float* Gr = (float*)(smem8 + OFF_GR);      // [64][72]

    const float* Wsrc = isA ? (role ? Wih1 : Wih0) : (role ? Whh1 : Whh0);
    const int KW  = isA ? (role ? 512 : 256) : 512;
    const int NCH = KW >> 6;                   // 4 or 8
    const float* bi = role ? bih1 : bih0;
    const float* bh = role ? bhh1 : bhh0;
    const float* cinit = role ? c01 : c00;

    // ---- one-time: weight half into SW128 fp16 tiles ----
    for (int idx = tid; idx < 64 * KW; idx += NTHR_) {
        const int n = idx / KW, k = idx - n * KW;
        const int grow = (n >> 4) * H_ + j0 + (n & 15);
        const float v = Wsrc[(size_t)grow * KW + k];
        const int tile = k >> 6, kk = k & 63;
        const uint32_t bo = n * 128 + kk * 2;
        const uint32_t sw = bo ^ ((bo >> 3) & 0x70);
        *(fp16*)(smem8 + OFF_WH + tile * 8192 + sw) = __float2half(v);
    }
    if (!isA && tid < 64) {
        const int grow = (tid >> 4) * H_ + j0 + (tid & 15);
        Bs[tid] = bi[grow] + bh[grow];
    }
    // B cells: m = tid&63, hidden jj0..jj0+3
    const int mcell = tid & 63;
    const int jj0 = (tid >> 6) * 4;
    float creg[4];
    if (!isA) {
        #pragma unroll
        for (int u = 0; u < 4; u++)
            creg[u] = cinit[(size_t)mcell * H_ + j0 + jj0 + u];
    }
    __syncthreads();

    // warp decomposition: 4 m16-tiles x 2 n-halves (each warp: 4 n8 tiles)
    const int mw = wid & 3;
    const int nw = wid >> 2;
    const int jA = lid >> 3, rA = lid & 7;
    const int rowA  = ((jA & 1) << 3) + rA;
    const int colA2 = (jA >> 1) << 4;
    const uint32_t swA = (uint32_t)rA << 4;
    const int rB = lid & 7;
    const int colB2 = ((lid >> 3) & 1) << 4;
    const uint32_t swB = (uint32_t)rB << 4;
    const uint32_t aBaseRow = (uint32_t)(16 * mw + rowA) * 128;
    const uint32_t bRow0 = (uint32_t)(32 * nw + ((lid & 16) ? 8 : 0) + rB) * 128;
    const uint32_t bRow1 = bRow0 + 16 * 128;

    float* yout = out;
    float* h1f  = out + (size_t)T_ * B_ * H_;
    float* c1f  = h1f + B_ * H_;
    float* h2f  = c1f + B_ * H_;
    float* c2f  = h2f + B_ * H_;
    float* hTd  = role ? h2f : h1f;
    float* cTd  = role ? c2f : c1f;

    for (int t = 0; t < T_; t++) {
        // ---- step-head dependency waits ----
        if (isA) {
            if (role == 0) {
                if (t >= 2 && tid == 0)
                    while (ld_acq(&g_done[0][slab * 32]) < t - 1) { }
            } else {
                if (tid < 32)
                    while (ld_acq(&g_done[0][tid * 32]) < t + 1) { }
                else if (tid == 32 && t >= 2)
                    while (ld_acq(&g_done[1][slab * 32]) < t - 1) { }
            }
            __syncthreads();
        } else {
            if (t >= 1) {
                if (tid < 32)
                    while (ld_acq(&g_done[role][tid * 32]) < t) { }
                __syncthreads();
            }
        }

        // ---- resolve source for this step ----
        const fp16* srcp;
        int rs;
        if (isA) {
            if (role == 0) { srcp = g_x16 + (size_t)t * B_ * C_; rs = C_; }
            else           { srcp = g_y016 + (size_t)t * B_ * H_; rs = H_; }
        } else {
            if (t == 0) srcp = role ? g_h0116 : g_h0016;
            else        srcp = (role ? g_h116 : g_y016) + (size_t)(t - 1) * B_ * H_;
            rs = H_;
        }

        float acc[4][4];
        #pragma unroll
        for (int j = 0; j < 4; j++)
            #pragma unroll
            for (int q = 0; q < 4; q++) acc[j][q] = 0.0f;

        // ---- staged chunk pipeline (ring 4, prologue 3) ----
        int issued = (NCH < 3) ? NCH : 3;
        for (int q = 0; q < issued; q++) {
            const uint32_t abase = sbA + (uint32_t)(q & 3) * 8192;
            #pragma unroll
            for (int it = 0; it < 2; it++) {
                const int seg = it * NTHR_ + tid;
                const int row = seg >> 3, s8 = seg & 7;
                const fp16* src = srcp + (size_t)row * rs + q * 64 + s8 * 8;
                const uint32_t bo = (uint32_t)(row * 128 + s8 * 16);
                const uint32_t sw = bo ^ ((bo >> 3) & 0x70);
                cp16(abase + sw, src);
            }
            cp_commit();
        }

        #pragma unroll 1
        for (int q = 0; q < NCH; q++) {
            const int ahead = issued - q - 1;
            if (ahead >= 2) cp_wait<2>();
            else if (ahead == 1) cp_wait<1>();
            else cp_wait<0>();
            __syncthreads();

            // ---- compute chunk q: 4 k-steps x (1 A ldsm + 2 W ldsm + 4 mma) ----
            {
                const uint32_t aBase = sbA + (uint32_t)(q & 3) * 8192;
                const uint32_t wT = sb + OFF_WH + (uint32_t)q * 8192;
                #pragma unroll
                for (int ks = 0; ks < 4; ks++) {
                    const uint32_t kA = (uint32_t)((ks * 32 + colA2) ^ (int)swA);
                    const uint32_t kB = (uint32_t)((ks * 32 + colB2) ^ (int)swB);
                    uint32_t af[4], w0[4], w1[4];
                    ldsm4(aBase + aBaseRow + kA, af);
                    ldsm4(wT + bRow0 + kB, w0);
                    ldsm4(wT + bRow1 + kB, w1);
                    mma16816h(acc[0], af, w0); mma16816h(acc[1], af, w0 + 2);
                    mma16816h(acc[2], af, w1); mma16816h(acc[3], af, w1 + 2);
                }
            }
            if (issued < NCH) {
                const int nq = issued;
                const uint32_t abase = sbA + (uint32_t)(nq & 3) * 8192;
                #pragma unroll
                for (int it = 0; it < 2; it++) {
                    const int seg = it * NTHR_ + tid;
                    const int row = seg >> 3, s8 = seg & 7;
                    const fp16* src = srcp + (size_t)row * rs + nq * 64 + s8 * 8;
                    const uint32_t bo = (uint32_t)(row * 128 + s8 * 16);
                    const uint32_t sw = bo ^ ((bo >> 3) & 0x70);
                    cp16(abase + sw, src);
                }
                cp_commit();
                issued++;
            }
        }
        __syncthreads();

        // ---- write gates to Gr[64][72] ----
        {
            const int mrow = 16 * mw + (lid >> 2);
            const int cbase = 32 * nw + 2 * (lid & 3);
            #pragma unroll
            for (int nt = 0; nt < 4; nt++) {
                const int cc = cbase + nt * 8;
                Gr[mrow * 72 + cc]           = acc[nt][0];
                Gr[mrow * 72 + cc + 1]       = acc[nt][1];
                Gr[(mrow + 8) * 72 + cc]     = acc[nt][2];
                Gr[(mrow + 8) * 72 + cc + 1] = acc[nt][3];
            }
        }
        __syncthreads();

        if (isA) {
            // ---- ship partial to scratch, ring flag ----
            float* sc = &g_part[role][slab][t & 1][0];
            const int row = tid >> 2, qq = tid & 3;
            const float* gsrc = Gr + row * 72 + qq * 16;
            float4* dst = (float4*)(sc + row * 64 + qq * 16);
            dst[0] = *(const float4*)(gsrc);
            dst[1] = *(const float4*)(gsrc + 4);
            dst[2] = *(const float4*)(gsrc + 8);
            dst[3] = *(const float4*)(gsrc + 12);
            __syncthreads();
            if (tid == 0) red_rel(&g_aflag[role][slab * 32]);
        } else {
            // ---- merge A partial ----
            if (tid == 0)
                while (ld_acq(&g_aflag[role][slab * 32]) < t + 1) { }
            __syncthreads();
            {
                const float* sc = &g_part[role][slab][t & 1][0];
                const int row = tid >> 2, qq = tid & 3;
                float* g = Gr + row * 72 + qq * 16;
                const float* s = sc + row * 64 + qq * 16;
                #pragma unroll
                for (int i = 0; i < 4; i++) {
                    float4 vs = *(const float4*)(s + 4 * i);
                    float4 vg = *(const float4*)(g + 4 * i);
                    vg.x += vs.x; vg.y += vs.y; vg.z += vs.z; vg.w += vs.w;
                    *(float4*)(g + 4 * i) = vg;
                }
            }
            __syncthreads();

            // ---- pointwise: 4 cells (m, jj0..jj0+3) ----
            float hv[4];
            #pragma unroll
            for (int u = 0; u < 4; u++) {
                const int nn = jj0 + u;
                float gi = Gr[mcell * 72 + nn]      + Bs[nn];
                float gf = Gr[mcell * 72 + 16 + nn] + Bs[16 + nn];
                float gg = Gr[mcell * 72 + 32 + nn] + Bs[32 + nn];
                float go = Gr[mcell * 72 + 48 + nn] + Bs[48 + nn];
                gi = sigf(gi); gf = sigf(gf); gg = tanhe(gg); go = sigf(go);
                const float cv = gf * creg[u] + gi * gg;
                creg[u] = cv;
                hv[u] = go * tanhe(cv);
            }
            // pack 4 cells into 2 u32 of fp16
            uint32_t ph[2];
            #pragma unroll
            for (int p2 = 0; p2 < 2; p2++) {
                const fp16 a = __float2half(hv[2 * p2]);
                const fp16 b = __float2half(hv[2 * p2 + 1]);
                ph[p2] = (uint32_t)__half_as_ushort(a) |
                         ((uint32_t)__half_as_ushort(b) << 16);
            }
            const size_t off = (size_t)t * B_ * H_ + (size_t)mcell * H_ + j0 + jj0;
            *(uint2*)((role ? g_h116 : g_y016) + off) = make_uint2(ph[0], ph[1]);
            if (role)
                *(float4*)(yout + off) = make_float4(hv[0], hv[1], hv[2], hv[3]);
            if (t == T_ - 1) {
                const size_t foff = (size_t)mcell * H_ + j0 + jj0;
                *(float4*)(hTd + foff) = make_float4(hv[0], hv[1], hv[2], hv[3]);
                *(float4*)(cTd + foff) = make_float4(creg[0], creg[1], creg[2], creg[3]);
            }
            __syncthreads();
            if (tid == 0) red_rel(&g_done[role][slab * 32]);
        }
    }
}

extern "C" void kernel_launch(void* const* d_in, const int* in_sizes, int n_in,
                              void* d_out, int out_size) {
    (void)in_sizes; (void)n_in; (void)out_size;
    cudaFuncSetAttribute(lstm_kernel, cudaFuncAttributeMaxDynamicSharedMemorySize,
                         SMEM_BYTES);
    prep_kernel<<<1024, 256>>>((const float*)d_in[0], (const float*)d_in[1],
                               (const float*)d_in[3]);
    lstm_kernel<<<GRID_, NTHR_, SMEM_BYTES>>>(
        (const float*)d_in[0],
        (const float*)d_in[1], (const float*)d_in[2],
        (const float*)d_in[3], (const float*)d_in[4],
        (const float*)d_in[5], (const float*)d_in[6],
        (const float*)d_in[7], (const float*)d_in[8],
        (const float*)d_in[9], (const float*)d_in[10],
        (const float*)d_in[11], (const float*)d_in[12],
        (float*)d_out);
}

// round 16
// speedup vs baseline: 2.2515x; 1.0413x over previous
#include <cuda_runtime.h>
#include <cuda_fp16.h>
#include <cstdint>
#include <cstddef>

// MultiLayerLSTM via mma.sync m16n8k16.f32.f16.f16.f32 (single-product fp16).
// K-SPLIT wavefront v2: per layer, 32 slabs of N=64 gates.
//   CTA-A: input-proj (x / y0) PLUS h*Whh[256..511]  -> ships one partial
//   CTA-B: h*Whh[0..255] (2 chunks of 128k) + merge + pointwise (recurrence)
// fp32 partial scratch (parity buffers + release flags); per-slab doorbells.

#define T_ 1024
#define B_ 64
#define C_ 256
#define H_ 512
#define NTHR_ 256
#define GRID_ 128

// ---- shared memory byte offsets ----
#define OFF_BS  0                  // 64 float biases (B only)
#define OFF_GR  256                // 64 x 72 float gate matrix
#define OFF_A   19456              // 4 x 16KB stage ring (2 SW128 sub-tiles each)
#define OFF_W   84992              // up to 12 x 8KB W fp16 tiles (64 rows x 64k)
#define SMEM_BYTES 183296

typedef __half fp16;

static __device__ __align__(256) fp16 g_x16[(size_t)T_ * B_ * C_];
static __device__ __align__(256) fp16 g_y016[(size_t)T_ * B_ * H_];
static __device__ __align__(256) fp16 g_h116[(size_t)T_ * B_ * H_];
static __device__ __align__(256) fp16 g_h0016[B_ * H_], g_h0116[B_ * H_];
static __device__ float g_part[2][32][2][4096];    // [layer][slab][parity][64m x 64n]
static __device__ int g_done[2][1024];             // per-slab doorbells, stride 32
static __device__ int g_aflag[2][1024];            // A->B partial flags, stride 32

__global__ void prep_kernel(const float* __restrict__ x,
                            const float* __restrict__ h00,
                            const float* __restrict__ h01) {
    const size_t stride = (size_t)gridDim.x * blockDim.x;
    const size_t i0 = (size_t)blockIdx.x * blockDim.x + threadIdx.x;
    const size_t nx = (size_t)T_ * B_ * C_;
    for (size_t p = i0; p < nx; p += stride)
        g_x16[p] = __float2half(x[p]);
    for (size_t p = i0; p < (size_t)B_ * H_; p += stride) {
        g_h0016[p] = __float2half(h00[p]);
        g_h0116[p] = __float2half(h01[p]);
    }
    for (size_t p = i0; p < 1024; p += stride) {
        g_done[0][p] = 0; g_done[1][p] = 0;
        g_aflag[0][p] = 0; g_aflag[1][p] = 0;
    }
}

__device__ __forceinline__ uint32_t smem_u32(const void* p) {
    uint32_t a;
    asm("{ .reg .u64 t; cvta.to.shared.u64 t, %1; cvt.u32.u64 %0, t; }"
        : "=r"(a) : "l"(p));
    return a;
}
__device__ __forceinline__ int ld_acq(const int* p) {
    int v;
    asm volatile(
        "{ .reg .u64 a; cvta.to.global.u64 a, %1; "
        "ld.acquire.gpu.global.b32 %0, [a]; }"
        : "=r"(v) : "l"(p) : "memory");
    return v;
}
__device__ __forceinline__ void red_rel(int* p) {
    asm volatile(
        "{ .reg .u64 a; cvta.to.global.u64 a, %1; "
        "red.release.gpu.global.add.u32 [a], %0; }"
        :: "r"(1), "l"(p) : "memory");
}
__device__ __forceinline__ void cp16(uint32_t daddr, const void* gptr) {
    asm volatile("cp.async.cg.shared.global [%0], [%1], 16;"
                 :: "r"(daddr), "l"(gptr) : "memory");
}
__device__ __forceinline__ void cp_commit() {
    asm volatile("cp.async.commit_group;" ::: "memory");
}
template <int N> __device__ __forceinline__ void cp_wait() {
    asm volatile("cp.async.wait_group %0;" :: "n"(N) : "memory");
}
__device__ __forceinline__ void ldsm4(uint32_t addr, uint32_t* r) {
    asm volatile("ldmatrix.sync.aligned.m8n8.x4.shared.b16 {%0,%1,%2,%3}, [%4];"
                 : "=r"(r[0]), "=r"(r[1]), "=r"(r[2]), "=r"(r[3]) : "r"(addr));
}
__device__ __forceinline__ void mma16816h(float* c, const uint32_t* a,
                                          const uint32_t* b) {
    asm volatile(
        "mma.sync.aligned.m16n8k16.row.col.f32.f16.f16.f32 "
        "{%0,%1,%2,%3}, {%4,%5,%6,%7}, {%8,%9}, {%0,%1,%2,%3};"
        : "+f"(c[0]), "+f"(c[1]), "+f"(c[2]), "+f"(c[3])
        : "r"(a[0]), "r"(a[1]), "r"(a[2]), "r"(a[3]), "r"(b[0]), "r"(b[1]));
}
__device__ __forceinline__ float sigf(float v) { return 1.0f / (1.0f + __expf(-v)); }
__device__ __forceinline__ float tanhe(float v) {
    const float e = __expf(2.0f * v);
    return 1.0f - 2.0f / (e + 1.0f);
}

extern __shared__ char smem8[];

// wait until all 32 slab counters of `bars` reach target (tid<32 poll)
__device__ __forceinline__ void wait_all(const int* bars, int tid, int target) {
    if (tid < 32)
        while (ld_acq(bars + tid * 32) < target) { }
    __syncthreads();
}

// stage one 128k chunk (64 rows) as two SW128 sub-tiles into ring slot `abase`
__device__ __forceinline__ void stage128(const fp16* __restrict__ srcp, int rs,
                                         int col0, int tid, uint32_t abase) {
    #pragma unroll
    for (int it = 0; it < 4; it++) {
        const int seg = it * NTHR_ + tid;            // 0..1023
        const int row = seg >> 4, s16 = seg & 15;
        const int st = s16 >> 3, s8 = s16 & 7;
        const fp16* src = srcp + (size_t)row * rs + col0 + st * 64 + s8 * 8;
        const uint32_t bo = (uint32_t)(row * 128 + s8 * 16);
        const uint32_t sw = bo ^ ((bo >> 3) & 0x70);
        cp16(abase + st * 8192 + sw, src);
    }
    cp_commit();
}

__global__ void __launch_bounds__(NTHR_, 1) lstm_kernel(
    const float* __restrict__ x,
    const float* __restrict__ h00, const float* __restrict__ c00,
    const float* __restrict__ h01, const float* __restrict__ c01,
    const float* __restrict__ Wih0, const float* __restrict__ Whh0,
    const float* __restrict__ bih0, const float* __restrict__ bhh0,
    const float* __restrict__ Wih1, const float* __restrict__ Whh1,
    const float* __restrict__ bih1, const float* __restrict__ bhh1,
    float* out)
{
    const int tid  = threadIdx.x;
    const int wid  = tid >> 5;
    const int lid  = tid & 31;
    const int bid  = blockIdx.x;
    const int role = bid >> 6;                 // layer 0 / 1
    const bool isA = ((bid >> 5) & 1) == 0;    // A: proj + h-upper, B: h-lower
    const int slab = bid & 31;                 // 32 slabs of N=64 gates
    const int j0   = slab * 16;                // hidden base of slab

    const uint32_t sb = smem_u32(smem8);
    const uint32_t sbA = sb + OFF_A;
    float* Bs = (float*)(smem8 + OFF_BS);
    float* Gr = (float*)(smem8 + OFF_GR);      // [64][72]

    const float* Wx = role ? Wih1 : Wih0;
    const float* Wh = role ? Whh1 : Whh0;
    const float* bi = role ? bih1 : bih0;
    const float* bh = role ? bhh1 : bhh0;
    const float* cinit = role ? c01 : c00;

    const int KP = role ? 512 : 256;           // proj K width (A only)
    const int KTOT = isA ? (KP + 256) : 256;   // this CTA's total K

    // ---- one-time: weights into SW128 fp16 tiles ----
    // A: tiles [0, KP/64) = Wih; tiles [KP/64, KP/64+4) = Whh cols 256..511
    // B: tiles [0, 4) = Whh cols 0..255
    for (int idx = tid; idx < 64 * KTOT; idx += NTHR_) {
        const int n = idx / KTOT, k = idx - n * KTOT;
        const int grow = (n >> 4) * H_ + j0 + (n & 15);
        float v; int tile;
        if (isA) {
            if (k < KP) { v = Wx[(size_t)grow * KP + k]; tile = k >> 6; }
            else {
                const int kh = k - KP + 256;
                v = Wh[(size_t)grow * H_ + kh];
                tile = (KP >> 6) + ((kh - 256) >> 6);
            }
        } else {
            v = Wh[(size_t)grow * H_ + k];
            tile = k >> 6;
        }
        const int kk = k & 63;
        const uint32_t bo = n * 128 + kk * 2;
        const uint32_t sw = bo ^ ((bo >> 3) & 0x70);
        *(fp16*)(smem8 + OFF_W + tile * 8192 + sw) = __float2half(v);
    }
    if (!isA && tid < 64) {
        const int grow = (tid >> 4) * H_ + j0 + (tid & 15);
        Bs[tid] = bi[grow] + bh[grow];
    }
    const int mcell = tid & 63;
    const int jj0 = (tid >> 6) * 4;
    float creg[4];
    if (!isA) {
        #pragma unroll
        for (int u = 0; u < 4; u++)
            creg[u] = cinit[(size_t)mcell * H_ + j0 + jj0 + u];
    }
    __syncthreads();

    // warp decomposition: 4 m16-tiles x 2 n-halves (each warp: 4 n8 tiles)
    const int mw = wid & 3;
    const int nw = wid >> 2;
    const int jA = lid >> 3, rA = lid & 7;
    const int rowA  = ((jA & 1) << 3) + rA;
    const int colA2 = (jA >> 1) << 4;
    const uint32_t swA = (uint32_t)rA << 4;
    const int rB = lid & 7;
    const int colB2 = ((lid >> 3) & 1) << 4;
    const uint32_t swB = (uint32_t)rB << 4;
    const uint32_t aBaseRow = (uint32_t)(16 * mw + rowA) * 128;
    const uint32_t bRow0 = (uint32_t)(32 * nw + ((lid & 16) ? 8 : 0) + rB) * 128;
    const uint32_t bRow1 = bRow0 + 16 * 128;

    float* yout = out;
    float* h1f  = out + (size_t)T_ * B_ * H_;
    float* c1f  = h1f + B_ * H_;
    float* h2f  = c1f + B_ * H_;
    float* c2f  = h2f + B_ * H_;
    float* hTd  = role ? h2f : h1f;
    float* cTd  = role ? c2f : c1f;

    const fp16* hist  = role ? g_h116 : g_y016;
    const fp16* hinit = role ? g_h0116 : g_h0016;

    float acc[4][4];

    // compute one 128k chunk: 2 sub-tiles x 4 k-steps
    #define COMPUTE2(slot, wtile)                                               \
        do {                                                                    \
            _Pragma("unroll")                                                   \
            for (int st = 0; st < 2; st++) {                                    \
                const uint32_t aB = sbA + (uint32_t)(slot) * 16384 + st * 8192; \
                const uint32_t wT = sb + OFF_W + ((uint32_t)(wtile) + st) * 8192;\
                _Pragma("unroll")                                               \
                for (int ks = 0; ks < 4; ks++) {                                \
                    const uint32_t kA = (uint32_t)((ks * 32 + colA2) ^ (int)swA);\
                    const uint32_t kB = (uint32_t)((ks * 32 + colB2) ^ (int)swB);\
                    uint32_t af[4], w0[4], w1[4];                               \
                    ldsm4(aB + aBaseRow + kA, af);                              \
                    ldsm4(wT + bRow0 + kB, w0);                                 \
                    ldsm4(wT + bRow1 + kB, w1);                                 \
                    mma16816h(acc[0], af, w0); mma16816h(acc[1], af, w0 + 2);   \
                    mma16816h(acc[2], af, w1); mma16816h(acc[3], af, w1 + 2);   \
                }                                                               \
            }                                                                   \
        } while (0)

    for (int t = 0; t < T_; t++) {
        #pragma unroll
        for (int j = 0; j < 4; j++)
            #pragma unroll
            for (int q = 0; q < 4; q++) acc[j][q] = 0.0f;

        if (isA) {
            // ---- phase 1: input projection (x or y0) ----
            const fp16* projp;
            int prs;
            if (role == 0) { projp = g_x16 + (size_t)t * B_ * C_; prs = C_; }
            else {
                wait_all(g_done[0], tid, t + 1);   // y0[t] ready
                projp = g_y016 + (size_t)t * B_ * H_; prs = H_;
            }
            if (role == 0) {
                stage128(projp, prs, 0, tid, sbA);
                stage128(projp, prs, 128, tid, sbA + 16384);
                cp_wait<1>(); __syncthreads();
                COMPUTE2(0, 0);
                cp_wait<0>(); __syncthreads();
                COMPUTE2(1, 2);
            } else {
                stage128(projp, prs, 0, tid, sbA);
                stage128(projp, prs, 128, tid, sbA + 16384);
                stage128(projp, prs, 256, tid, sbA + 32768);
                stage128(projp, prs, 384, tid, sbA + 49152);
                cp_wait<3>(); __syncthreads();
                COMPUTE2(0, 0);
                cp_wait<2>(); __syncthreads();
                COMPUTE2(1, 2);
                cp_wait<1>(); __syncthreads();
                COMPUTE2(2, 4);
                cp_wait<0>(); __syncthreads();
                COMPUTE2(3, 6);
            }

            // ---- phase 2: h * Whh[256..511] ----
            wait_all(g_done[role], tid, t);        // h[t-1] ready (all slabs)
            const fp16* hp = (t == 0) ? hinit : (hist + (size_t)(t - 1) * B_ * H_);
            stage128(hp, H_, 256, tid, sbA);
            stage128(hp, H_, 384, tid, sbA + 16384);
            const int htile = KP >> 6;             // 4 or 8
            cp_wait<1>(); __syncthreads();
            COMPUTE2(0, htile);
            cp_wait<0>(); __syncthreads();
            COMPUTE2(1, htile + 2);

            // ---- write gates to Gr, ship partial, flag ----
            {
                const int mrow = 16 * mw + (lid >> 2);
                const int cbase = 32 * nw + 2 * (lid & 3);
                #pragma unroll
                for (int nt = 0; nt < 4; nt++) {
                    const int cc = cbase + nt * 8;
                    Gr[mrow * 72 + cc]           = acc[nt][0];
                    Gr[mrow * 72 + cc + 1]       = acc[nt][1];
                    Gr[(mrow + 8) * 72 + cc]     = acc[nt][2];
                    Gr[(mrow + 8) * 72 + cc + 1] = acc[nt][3];
                }
            }
            __syncthreads();
            {
                float* sc = &g_part[role][slab][t & 1][0];
                const int row = tid >> 2, qq = tid & 3;
                const float* gsrc = Gr + row * 72 + qq * 16;
                float4* dst = (float4*)(sc + row * 64 + qq * 16);
                dst[0] = *(const float4*)(gsrc);
                dst[1] = *(const float4*)(gsrc + 4);
                dst[2] = *(const float4*)(gsrc + 8);
                dst[3] = *(const float4*)(gsrc + 12);
            }
            __syncthreads();
            if (tid == 0) red_rel(&g_aflag[role][slab * 32]);
        } else {
            // ---- B: h * Whh[0..255] (2 chunks), merge, pointwise ----
            if (t >= 1) wait_all(g_done[role], tid, t);
            const fp16* hp = (t == 0) ? hinit : (hist + (size_t)(t - 1) * B_ * H_);
            stage128(hp, H_, 0, tid, sbA);
            stage128(hp, H_, 128, tid, sbA + 16384);
            cp_wait<1>(); __syncthreads();
            COMPUTE2(0, 0);
            cp_wait<0>(); __syncthreads();
            COMPUTE2(1, 2);

            // write own gates to Gr
            {
                const int mrow = 16 * mw + (lid >> 2);
                const int cbase = 32 * nw + 2 * (lid & 3);
                #pragma unroll
                for (int nt = 0; nt < 4; nt++) {
                    const int cc = cbase + nt * 8;
                    Gr[mrow * 72 + cc]           = acc[nt][0];
                    Gr[mrow * 72 + cc + 1]       = acc[nt][1];
                    Gr[(mrow + 8) * 72 + cc]     = acc[nt][2];
                    Gr[(mrow + 8) * 72 + cc + 1] = acc[nt][3];
                }
            }
            __syncthreads();

            // merge A partial (proj + h-upper)
            if (tid == 0)
                while (ld_acq(&g_aflag[role][slab * 32]) < t + 1) { }
            __syncthreads();
            {
                const float* sc = &g_part[role][slab][t & 1][0];
                const int row = tid >> 2, qq = tid & 3;
                float* g = Gr + row * 72 + qq * 16;
                const float* s = sc + row * 64 + qq * 16;
                #pragma unroll
                for (int i = 0; i < 4; i++) {
                    float4 vs = *(const float4*)(s + 4 * i);
                    float4 vg = *(const float4*)(g + 4 * i);
                    vg.x += vs.x; vg.y += vs.y; vg.z += vs.z; vg.w += vs.w;
                    *(float4*)(g + 4 * i) = vg;
                }
            }
            __syncthreads();

            // pointwise: 4 cells (m, jj0..jj0+3)
            float hv[4];
            #pragma unroll
            for (int u = 0; u < 4; u++) {
                const int nn = jj0 + u;
                float gi = Gr[mcell * 72 + nn]      + Bs[nn];
                float gf = Gr[mcell * 72 + 16 + nn] + Bs[16 + nn];
                float gg = Gr[mcell * 72 + 32 + nn] + Bs[32 + nn];
                float go = Gr[mcell * 72 + 48 + nn] + Bs[48 + nn];
                gi = sigf(gi); gf = sigf(gf); gg = tanhe(gg); go = sigf(go);
                const float cv = gf * creg[u] + gi * gg;
                creg[u] = cv;
                hv[u] = go * tanhe(cv);
            }
            uint32_t ph[2];
            #pragma unroll
            for (int p2 = 0; p2 < 2; p2++) {
                const fp16 a = __float2half(hv[2 * p2]);
                const fp16 b = __float2half(hv[2 * p2 + 1]);
                ph[p2] = (uint32_t)__half_as_ushort(a) |
                         ((uint32_t)__half_as_ushort(b) << 16);
            }
            const size_t off = (size_t)t * B_ * H_ + (size_t)mcell * H_ + j0 + jj0;
            *(uint2*)((role ? g_h116 : g_y016) + off) = make_uint2(ph[0], ph[1]);
            if (role)
                *(float4*)(yout + off) = make_float4(hv[0], hv[1], hv[2], hv[3]);
            if (t == T_ - 1) {
                const size_t foff = (size_t)mcell * H_ + j0 + jj0;
                *(float4*)(hTd + foff) = make_float4(hv[0], hv[1], hv[2], hv[3]);
                *(float4*)(cTd + foff) = make_float4(creg[0], creg[1], creg[2], creg[3]);
            }
            __syncthreads();
            if (tid == 0) red_rel(&g_done[role][slab * 32]);
        }
    }
    #undef COMPUTE2
}

extern "C" void kernel_launch(void* const* d_in, const int* in_sizes, int n_in,
                              void* d_out, int out_size) {
    (void)in_sizes; (void)n_in; (void)out_size;
    cudaFuncSetAttribute(lstm_kernel, cudaFuncAttributeMaxDynamicSharedMemorySize,
                         SMEM_BYTES);
    prep_kernel<<<1024, 256>>>((const float*)d_in[0], (const float*)d_in[1],
                               (const float*)d_in[3]);
    lstm_kernel<<<GRID_, NTHR_, SMEM_BYTES>>>(
        (const float*)d_in[0],
        (const float*)d_in[1], (const float*)d_in[2],
        (const float*)d_in[3], (const float*)d_in[4],
        (const float*)d_in[5], (const float*)d_in[6],
        (const float*)d_in[7], (const float*)d_in[8],
        (const float*)d_in[9], (const float*)d_in[10],
        (const float*)d_in[11], (const float*)d_in[12],
        (float*)d_out);
}

// round 17
// speedup vs baseline: 2.4883x; 1.1052x over previous
#include <cuda_runtime.h>
#include <cuda_fp16.h>
#include <cstdint>
#include <cstddef>

// MultiLayerLSTM via mma.sync m16n8k16.f32.f16.f16.f32 (single-product fp16).
// K-SPLIT wavefront v3: per layer, 32 slabs of N=64 gates.
//   CTA-B: ALL of h*Whh (4 chunks of 128k) + merge + pointwise  (recurrence)
//   CTA-A: input projection only (x / y0) -> ships partial via L2 scratch
// A has parity backpressure (own slab doorbell >= t-1). Per-slab doorbells.

#define T_ 1024
#define B_ 64
#define C_ 256
#define H_ 512
#define NTHR_ 256
#define GRID_ 128

// ---- shared memory byte offsets ----
#define OFF_BS  0                  // 64 float biases (B only)
#define OFF_GR  256                // 64 x 72 float gate matrix
#define OFF_A   19456              // 4 x 16KB stage ring (2 SW128 sub-tiles each)
#define OFF_W   84992              // 8 x 8KB W fp16 tiles (64 rows x 64k)
#define SMEM_BYTES 150784

typedef __half fp16;

static __device__ __align__(256) fp16 g_x16[(size_t)T_ * B_ * C_];
static __device__ __align__(256) fp16 g_y016[(size_t)T_ * B_ * H_];
static __device__ __align__(256) fp16 g_h116[(size_t)T_ * B_ * H_];
static __device__ __align__(256) fp16 g_h0016[B_ * H_], g_h0116[B_ * H_];
static __device__ float g_part[2][32][2][4096];    // [layer][slab][parity][64m x 64n]
static __device__ int g_done[2][1024];             // per-slab doorbells, stride 32
static __device__ int g_aflag[2][1024];            // A->B partial flags, stride 32

__global__ void prep_kernel(const float* __restrict__ x,
                            const float* __restrict__ h00,
                            const float* __restrict__ h01) {
    const size_t stride = (size_t)gridDim.x * blockDim.x;
    const size_t i0 = (size_t)blockIdx.x * blockDim.x + threadIdx.x;
    const size_t nx = (size_t)T_ * B_ * C_;
    for (size_t p = i0; p < nx; p += stride)
        g_x16[p] = __float2half(x[p]);
    for (size_t p = i0; p < (size_t)B_ * H_; p += stride) {
        g_h0016[p] = __float2half(h00[p]);
        g_h0116[p] = __float2half(h01[p]);
    }
    for (size_t p = i0; p < 1024; p += stride) {
        g_done[0][p] = 0; g_done[1][p] = 0;
        g_aflag[0][p] = 0; g_aflag[1][p] = 0;
    }
}

__device__ __forceinline__ uint32_t smem_u32(const void* p) {
    uint32_t a;
    asm("{ .reg .u64 t; cvta.to.shared.u64 t, %1; cvt.u32.u64 %0, t; }"
        : "=r"(a) : "l"(p));
    return a;
}
__device__ __forceinline__ int ld_acq(const int* p) {
    int v;
    asm volatile(
        "{ .reg .u64 a; cvta.to.global.u64 a, %1; "
        "ld.acquire.gpu.global.b32 %0, [a]; }"
        : "=r"(v) : "l"(p) : "memory");
    return v;
}
__device__ __forceinline__ void red_rel(int* p) {
    asm volatile(
        "{ .reg .u64 a; cvta.to.global.u64 a, %1; "
        "red.release.gpu.global.add.u32 [a], %0; }"
        :: "r"(1), "l"(p) : "memory");
}
__device__ __forceinline__ void cp16(uint32_t daddr, const void* gptr) {
    asm volatile("cp.async.cg.shared.global [%0], [%1], 16;"
                 :: "r"(daddr), "l"(gptr) : "memory");
}
__device__ __forceinline__ void cp_commit() {
    asm volatile("cp.async.commit_group;" ::: "memory");
}
template <int N> __device__ __forceinline__ void cp_wait() {
    asm volatile("cp.async.wait_group %0;" :: "n"(N) : "memory");
}
__device__ __forceinline__ void ldsm4(uint32_t addr, uint32_t* r) {
    asm volatile("ldmatrix.sync.aligned.m8n8.x4.shared.b16 {%0,%1,%2,%3}, [%4];"
                 : "=r"(r[0]), "=r"(r[1]), "=r"(r[2]), "=r"(r[3]) : "r"(addr));
}
__device__ __forceinline__ void mma16816h(float* c, const uint32_t* a,
                                          const uint32_t* b) {
    asm volatile(
        "mma.sync.aligned.m16n8k16.row.col.f32.f16.f16.f32 "
        "{%0,%1,%2,%3}, {%4,%5,%6,%7}, {%8,%9}, {%0,%1,%2,%3};"
        : "+f"(c[0]), "+f"(c[1]), "+f"(c[2]), "+f"(c[3])
        : "r"(a[0]), "r"(a[1]), "r"(a[2]), "r"(a[3]), "r"(b[0]), "r"(b[1]));
}
__device__ __forceinline__ float sigf(float v) { return 1.0f / (1.0f + __expf(-v)); }
__device__ __forceinline__ float tanhe(float v) {
    const float e = __expf(2.0f * v);
    return 1.0f - 2.0f / (e + 1.0f);
}

extern __shared__ char smem8[];

// wait until all 32 slab counters of `bars` reach target (tid<32 poll)
__device__ __forceinline__ void wait_all(const int* bars, int tid, int target) {
    if (tid < 32)
        while (ld_acq(bars + tid * 32) < target) { }
    __syncthreads();
}

// stage one 128k chunk (64 rows) as two SW128 sub-tiles into ring slot `abase`
__device__ __forceinline__ void stage128(const fp16* __restrict__ srcp, int rs,
                                         int col0, int tid, uint32_t abase) {
    #pragma unroll
    for (int it = 0; it < 4; it++) {
        const int seg = it * NTHR_ + tid;            // 0..1023
        const int row = seg >> 4, s16 = seg & 15;
        const int st = s16 >> 3, s8 = s16 & 7;
        const fp16* src = srcp + (size_t)row * rs + col0 + st * 64 + s8 * 8;
        const uint32_t bo = (uint32_t)(row * 128 + s8 * 16);
        const uint32_t sw = bo ^ ((bo >> 3) & 0x70);
        cp16(abase + st * 8192 + sw, src);
    }
    cp_commit();
}

__global__ void __launch_bounds__(NTHR_, 1) lstm_kernel(
    const float* __restrict__ x,
    const float* __restrict__ h00, const float* __restrict__ c00,
    const float* __restrict__ h01, const float* __restrict__ c01,
    const float* __restrict__ Wih0, const float* __restrict__ Whh0,
    const float* __restrict__ bih0, const float* __restrict__ bhh0,
    const float* __restrict__ Wih1, const float* __restrict__ Whh1,
    const float* __restrict__ bih1, const float* __restrict__ bhh1,
    float* out)
{
    const int tid  = threadIdx.x;
    const int wid  = tid >> 5;
    const int lid  = tid & 31;
    const int bid  = blockIdx.x;
    const int role = bid >> 6;                 // layer 0 / 1
    const bool isA = ((bid >> 5) & 1) == 0;    // A: projection, B: recurrence
    const int slab = bid & 31;                 // 32 slabs of N=64 gates
    const int j0   = slab * 16;                // hidden base of slab

    const uint32_t sb = smem_u32(smem8);
    const uint32_t sbA = sb + OFF_A;
    float* Bs = (float*)(smem8 + OFF_BS);
    float* Gr = (float*)(smem8 + OFF_GR);      // [64][72]

    const float* Wx = role ? Wih1 : Wih0;
    const float* Wh = role ? Whh1 : Whh0;
    const float* bi = role ? bih1 : bih0;
    const float* bh = role ? bhh1 : bhh0;
    const float* cinit = role ? c01 : c00;

    const int KP = role ? 512 : 256;           // proj K width (A only)
    const int KTOT = isA ? KP : 512;           // this CTA's K

    // ---- one-time: weights into SW128 fp16 tiles ----
    for (int idx = tid; idx < 64 * KTOT; idx += NTHR_) {
        const int n = idx / KTOT, k = idx - n * KTOT;
        const int grow = (n >> 4) * H_ + j0 + (n & 15);
        const float v = isA ? Wx[(size_t)grow * KP + k]
                            : Wh[(size_t)grow * H_ + k];
        const int tile = k >> 6, kk = k & 63;
        const uint32_t bo = n * 128 + kk * 2;
        const uint32_t sw = bo ^ ((bo >> 3) & 0x70);
        *(fp16*)(smem8 + OFF_W + tile * 8192 + sw) = __float2half(v);
    }
    if (!isA && tid < 64) {
        const int grow = (tid >> 4) * H_ + j0 + (tid & 15);
        Bs[tid] = bi[grow] + bh[grow];
    }
    const int mcell = tid & 63;
    const int jj0 = (tid >> 6) * 4;
    float creg[4];
    if (!isA) {
        #pragma unroll
        for (int u = 0; u < 4; u++)
            creg[u] = cinit[(size_t)mcell * H_ + j0 + jj0 + u];
    }
    __syncthreads();

    // warp decomposition: 4 m16-tiles x 2 n-halves (each warp: 4 n8 tiles)
    const int mw = wid & 3;
    const int nw = wid >> 2;
    const int jA = lid >> 3, rA = lid & 7;
    const int rowA  = ((jA & 1) << 3) + rA;
    const int colA2 = (jA >> 1) << 4;
    const uint32_t swA = (uint32_t)rA << 4;
    const int rB = lid & 7;
    const int colB2 = ((lid >> 3) & 1) << 4;
    const uint32_t swB = (uint32_t)rB << 4;
    const uint32_t aBaseRow = (uint32_t)(16 * mw + rowA) * 128;
    const uint32_t bRow0 = (uint32_t)(32 * nw + ((lid & 16) ? 8 : 0) + rB) * 128;
    const uint32_t bRow1 = bRow0 + 16 * 128;

    float* yout = out;
    float* h1f  = out + (size_t)T_ * B_ * H_;
    float* c1f  = h1f + B_ * H_;
    float* h2f  = c1f + B_ * H_;
    float* c2f  = h2f + B_ * H_;
    float* hTd  = role ? h2f : h1f;
    float* cTd  = role ? c2f : c1f;

    const fp16* hist  = role ? g_h116 : g_y016;
    const fp16* hinit = role ? g_h0116 : g_h0016;

    float acc[4][4];

    // compute one 128k chunk: 2 sub-tiles x 4 k-steps
    #define COMPUTE2(slot, wtile)                                               \
        do {                                                                    \
            _Pragma("unroll")                                                   \
            for (int st = 0; st < 2; st++) {                                    \
                const uint32_t aB = sbA + (uint32_t)(slot) * 16384 + st * 8192; \
                const uint32_t wT = sb + OFF_W + ((uint32_t)(wtile) + st) * 8192;\
                _Pragma("unroll")                                               \
                for (int ks = 0; ks < 4; ks++) {                                \
                    const uint32_t kA = (uint32_t)((ks * 32 + colA2) ^ (int)swA);\
                    const uint32_t kB = (uint32_t)((ks * 32 + colB2) ^ (int)swB);\
                    uint32_t af[4], w0[4], w1[4];                               \
                    ldsm4(aB + aBaseRow + kA, af);                              \
                    ldsm4(wT + bRow0 + kB, w0);                                 \
                    ldsm4(wT + bRow1 + kB, w1);                                 \
                    mma16816h(acc[0], af, w0); mma16816h(acc[1], af, w0 + 2);   \
                    mma16816h(acc[2], af, w1); mma16816h(acc[3], af, w1 + 2);   \
                }                                                               \
            }                                                                   \
        } while (0)

    for (int t = 0; t < T_; t++) {
        #pragma unroll
        for (int j = 0; j < 4; j++)
            #pragma unroll
            for (int q = 0; q < 4; q++) acc[j][q] = 0.0f;

        if (isA) {
            // ---- parity backpressure: B must have consumed partial t-2 ----
            if (t >= 2) {
                if (tid == 0)
                    while (ld_acq(&g_done[role][slab * 32]) < t - 1) { }
                __syncthreads();
            }
            // ---- input projection (x or y0) ----
            const fp16* projp;
            int prs;
            if (role == 0) { projp = g_x16 + (size_t)t * B_ * C_; prs = C_; }
            else {
                wait_all(g_done[0], tid, t + 1);   // y0[t] ready
                projp = g_y016 + (size_t)t * B_ * H_; prs = H_;
            }
            if (role == 0) {
                stage128(projp, prs, 0, tid, sbA);
                stage128(projp, prs, 128, tid, sbA + 16384);
                cp_wait<1>(); __syncthreads();
                COMPUTE2(0, 0);
                cp_wait<0>(); __syncthreads();
                COMPUTE2(1, 2);
            } else {
                stage128(projp, prs, 0, tid, sbA);
                stage128(projp, prs, 128, tid, sbA + 16384);
                stage128(projp, prs, 256, tid, sbA + 32768);
                stage128(projp, prs, 384, tid, sbA + 49152);
                cp_wait<3>(); __syncthreads();
                COMPUTE2(0, 0);
                cp_wait<2>(); __syncthreads();
                COMPUTE2(1, 2);
                cp_wait<1>(); __syncthreads();
                COMPUTE2(2, 4);
                cp_wait<0>(); __syncthreads();
                COMPUTE2(3, 6);
            }

            // ---- write gates to Gr, ship partial, flag ----
            {
                const int mrow = 16 * mw + (lid >> 2);
                const int cbase = 32 * nw + 2 * (lid & 3);
                #pragma unroll
                for (int nt = 0; nt < 4; nt++) {
                    const int cc = cbase + nt * 8;
                    Gr[mrow * 72 + cc]           = acc[nt][0];
                    Gr[mrow * 72 + cc + 1]       = acc[nt][1];
                    Gr[(mrow + 8) * 72 + cc]     = acc[nt][2];
                    Gr[(mrow + 8) * 72 + cc + 1] = acc[nt][3];
                }
            }
            __syncthreads();
            {
                float* sc = &g_part[role][slab][t & 1][0];
                const int row = tid >> 2, qq = tid & 3;
                const float* gsrc = Gr + row * 72 + qq * 16;
                float4* dst = (float4*)(sc + row * 64 + qq * 16);
                dst[0] = *(const float4*)(gsrc);
                dst[1] = *(const float4*)(gsrc + 4);
                dst[2] = *(const float4*)(gsrc + 8);
                dst[3] = *(const float4*)(gsrc + 12);
            }
            __syncthreads();
            if (tid == 0) red_rel(&g_aflag[role][slab * 32]);
        } else {
            // ---- B: full h*Whh (4 chunks of 128k), merge, pointwise ----
            if (t >= 1) wait_all(g_done[role], tid, t);
            const fp16* hp = (t == 0) ? hinit : (hist + (size_t)(t - 1) * B_ * H_);
            stage128(hp, H_, 0, tid, sbA);
            stage128(hp, H_, 128, tid, sbA + 16384);
            stage128(hp, H_, 256, tid, sbA + 32768);
            stage128(hp, H_, 384, tid, sbA + 49152);
            cp_wait<3>(); __syncthreads();
            COMPUTE2(0, 0);
            cp_wait<2>(); __syncthreads();
            COMPUTE2(1, 2);
            cp_wait<1>(); __syncthreads();
            COMPUTE2(2, 4);
            cp_wait<0>(); __syncthreads();
            COMPUTE2(3, 6);

            // write own gates to Gr
            {
                const int mrow = 16 * mw + (lid >> 2);
                const int cbase = 32 * nw + 2 * (lid & 3);
                #pragma unroll
                for (int nt = 0; nt < 4; nt++) {
                    const int cc = cbase + nt * 8;
                    Gr[mrow * 72 + cc]           = acc[nt][0];
                    Gr[mrow * 72 + cc + 1]       = acc[nt][1];
                    Gr[(mrow + 8) * 72 + cc]     = acc[nt][2];
                    Gr[(mrow + 8) * 72 + cc + 1] = acc[nt][3];
                }
            }
            __syncthreads();

            // merge A's projection partial (ready well in advance)
            if (tid == 0)
                while (ld_acq(&g_aflag[role][slab * 32]) < t + 1) { }
            __syncthreads();
            {
                const float* sc = &g_part[role][slab][t & 1][0];
                const int row = tid >> 2, qq = tid & 3;
                float* g = Gr + row * 72 + qq * 16;
                const float* s = sc + row * 64 + qq * 16;
                #pragma unroll
                for (int i = 0; i < 4; i++) {
                    float4 vs = *(const float4*)(s + 4 * i);
                    float4 vg = *(const float4*)(g + 4 * i);
                    vg.x += vs.x; vg.y += vs.y; vg.z += vs.z; vg.w += vs.w;
                    *(float4*)(g + 4 * i) = vg;
                }
            }
            __syncthreads();

            // pointwise: 4 cells (m, jj0..jj0+3)
            float hv[4];
            #pragma unroll
            for (int u = 0; u < 4; u++) {
                const int nn = jj0 + u;
                float gi = Gr[mcell * 72 + nn]      + Bs[nn];
                float gf = Gr[mcell * 72 + 16 + nn] + Bs[16 + nn];
                float gg = Gr[mcell * 72 + 32 + nn] + Bs[32 + nn];
                float go = Gr[mcell * 72 + 48 + nn] + Bs[48 + nn];
                gi = sigf(gi); gf = sigf(gf); gg = tanhe(gg); go = sigf(go);
                const float cv = gf * creg[u] + gi * gg;
                creg[u] = cv;
                hv[u] = go * tanhe(cv);
            }
            uint32_t ph[2];
            #pragma unroll
            for (int p2 = 0; p2 < 2; p2++) {
                const fp16 a = __float2half(hv[2 * p2]);
                const fp16 b = __float2half(hv[2 * p2 + 1]);
                ph[p2] = (uint32_t)__half_as_ushort(a) |
                         ((uint32_t)__half_as_ushort(b) << 16);
            }
            const size_t off = (size_t)t * B_ * H_ + (size_t)mcell * H_ + j0 + jj0;
            *(uint2*)((role ? g_h116 : g_y016) + off) = make_uint2(ph[0], ph[1]);
            if (role)
                *(float4*)(yout + off) = make_float4(hv[0], hv[1], hv[2], hv[3]);
            if (t == T_ - 1) {
                const size_t foff = (size_t)mcell * H_ + j0 + jj0;
                *(float4*)(hTd + foff) = make_float4(hv[0], hv[1], hv[2], hv[3]);
                *(float4*)(cTd + foff) = make_float4(creg[0], creg[1], creg[2], creg[3]);
            }
            __syncthreads();
            if (tid == 0) red_rel(&g_done[role][slab * 32]);
        }
    }
    #undef COMPUTE2
}

extern "C" void kernel_launch(void* const* d_in, const int* in_sizes, int n_in,
                              void* d_out, int out_size) {
    (void)in_sizes; (void)n_in; (void)out_size;
    cudaFuncSetAttribute(lstm_kernel, cudaFuncAttributeMaxDynamicSharedMemorySize,
                         SMEM_BYTES);
    prep_kernel<<<1024, 256>>>((const float*)d_in[0], (const float*)d_in[1],
                               (const float*)d_in[3]);
    lstm_kernel<<<GRID_, NTHR_, SMEM_BYTES>>>(
        (const float*)d_in[0],
        (const float*)d_in[1], (const float*)d_in[2],
        (const float*)d_in[3], (const float*)d_in[4],
        (const float*)d_in[5], (const float*)d_in[6],
        (const float*)d_in[7], (const float*)d_in[8],
        (const float*)d_in[9], (const float*)d_in[10],
        (const float*)d_in[11], (const float*)d_in[12],
        (float*)d_out);
}